// round 15
// baseline (speedup 1.0000x reference)
#include <cuda_runtime.h>
#include <cuda_fp16.h>
#include <cstdint>
#include <cstddef>

#define E_DIM  1024
#define NHEAD  16
#define HDIM   64
#define BATCH  2
#define SEQ_Q  1024
#define SEQ_KV 4096
#define LN_EPS 1e-5f
#define SM_SHIFT 8.0f
#define IDXCAP 4160

// ---------------- scratch (no allocations allowed) ----------------
__device__ __half g_qh  [(size_t)BATCH * SEQ_Q * E_DIM];
__device__ __half g_kvc [(size_t)BATCH * IDXCAP * E_DIM];
__device__ __half g_wh  [(size_t)4 * E_DIM * E_DIM];
__device__ __half g_Qp  [(size_t)BATCH * NHEAD * SEQ_Q * HDIM];
__device__ __half g_Kp  [(size_t)BATCH * NHEAD * SEQ_KV * HDIM];
__device__ __half g_Vp  [(size_t)BATCH * NHEAD * SEQ_KV * HDIM];
__device__ __half g_attnh[(size_t)BATCH * SEQ_Q * E_DIM];
__device__ float  g_proj[(size_t)BATCH * SEQ_Q * E_DIM];
__device__ float  g_oacc[2][(size_t)BATCH * NHEAD * SEQ_Q * HDIM];  // split-KV partial O
__device__ float  g_lacc[2][(size_t)BATCH * NHEAD * SEQ_Q];          // split-KV partial l
__device__ int    g_idx [BATCH][IDXCAP];
__device__ float  g_bias[BATCH][IDXCAP];
__device__ int    g_ntiles[BATCH];

// ---------------- helpers ----------------
__device__ __forceinline__ void mma16(float* c, const unsigned* a, unsigned b0, unsigned b1) {
    asm volatile(
        "mma.sync.aligned.m16n8k16.row.col.f32.f16.f16.f32 "
        "{%0,%1,%2,%3}, {%4,%5,%6,%7}, {%8,%9}, {%0,%1,%2,%3};\n"
        : "+f"(c[0]), "+f"(c[1]), "+f"(c[2]), "+f"(c[3])
        : "r"(a[0]), "r"(a[1]), "r"(a[2]), "r"(a[3]), "r"(b0), "r"(b1));
}

__device__ __forceinline__ void ldsm4(unsigned* r, uint32_t addr) {
    asm volatile("ldmatrix.sync.aligned.m8n8.x4.shared.b16 {%0,%1,%2,%3}, [%4];"
                 : "=r"(r[0]), "=r"(r[1]), "=r"(r[2]), "=r"(r[3]) : "r"(addr));
}

__device__ __forceinline__ void cpasync16h(const __half* dst, const __half* src) {
    uint32_t d = (uint32_t)__cvta_generic_to_shared(dst);
    asm volatile("cp.async.cg.shared.global [%0], [%1], 16;" :: "r"(d), "l"(src));
}
#define CP_COMMIT() asm volatile("cp.async.commit_group;" ::: "memory")
#define CP_WAIT(n)  asm volatile("cp.async.wait_group %0;" :: "n"(n) : "memory")

// ---------------- conversion kernels (high-MLP) ----------------
__global__ void __launch_bounds__(256) conv_one(const float* __restrict__ in,
                                                __half* __restrict__ out) {
    int base = blockIdx.x * 1024 + threadIdx.x;
#pragma unroll
    for (int j = 0; j < 4; j++) {
        int i = base + j * 256;
        float4 v = ((const float4*)in)[i];
        __half2* o = (__half2*)out + i * 2;
        o[0] = __float22half2_rn(make_float2(v.x, v.y));
        o[1] = __float22half2_rn(make_float2(v.z, v.w));
    }
}

__global__ void __launch_bounds__(256) conv_w(const float* __restrict__ a,
                                              const float* __restrict__ b,
                                              const float* __restrict__ c,
                                              const float* __restrict__ d,
                                              __half* __restrict__ o) {
    const float* in = (blockIdx.y == 0) ? a : (blockIdx.y == 1) ? b : (blockIdx.y == 2) ? c : d;
    __half* out = o + (size_t)blockIdx.y * E_DIM * E_DIM;
    int base = blockIdx.x * 1024 + threadIdx.x;
#pragma unroll
    for (int j = 0; j < 4; j++) {
        int i = base + j * 256;
        float4 v = ((const float4*)in)[i];
        __half2* op = (__half2*)out + i * 2;
        op[0] = __float22half2_rn(make_float2(v.x, v.y));
        op[1] = __float22half2_rn(make_float2(v.z, v.w));
    }
}

// gather+convert: 8 rows/CTA, 32 threads/row, 8 independent float4 per thread
__global__ void __launch_bounds__(256) conv_kvc(const float* __restrict__ kv) {
    const int b = blockIdx.y;
    const int rbase = blockIdx.x * 8;
    if (rbase >= g_ntiles[b] * 64) return;
    const int rloc = threadIdx.x >> 5;
    const int t32  = threadIdx.x & 31;
    const int row  = rbase + rloc;
    const int src  = g_idx[b][row];
    const float4* sp = (const float4*)(kv + ((size_t)b * SEQ_KV + src) * E_DIM) + t32;
    __half2* dp = (__half2*)(g_kvc + ((size_t)b * IDXCAP + row) * E_DIM) + t32 * 2;
#pragma unroll
    for (int j = 0; j < 8; j++) {
        float4 v = sp[j * 32];
        dp[j * 64]     = __float22half2_rn(make_float2(v.x, v.y));
        dp[j * 64 + 1] = __float22half2_rn(make_float2(v.z, v.w));
    }
}

// ---------------- mask compaction ----------------
__global__ void __launch_bounds__(1024) compact_kernel(const int* __restrict__ mask) {
    const int b   = blockIdx.x;
    const int tid = threadIdx.x;
    const int lane = tid & 31, warp = tid >> 5;
    const int* m = mask + (size_t)b * SEQ_KV;
    __shared__ int warpSums[32];

    int v[4];
    int base = tid * 4;
    int cnt = 0;
#pragma unroll
    for (int i = 0; i < 4; i++) { v[i] = (m[base + i] != 0); cnt += v[i]; }

    int x = cnt;
#pragma unroll
    for (int off = 1; off < 32; off <<= 1) {
        int y = __shfl_up_sync(0xffffffffu, x, off);
        if (lane >= off) x += y;
    }
    if (lane == 31) warpSums[warp] = x;
    __syncthreads();
    if (warp == 0) {
        int wsum = warpSums[lane];
#pragma unroll
        for (int off = 1; off < 32; off <<= 1) {
            int y = __shfl_up_sync(0xffffffffu, wsum, off);
            if (lane >= off) wsum += y;
        }
        warpSums[lane] = wsum;
    }
    __syncthreads();
    int warpBase = (warp == 0) ? 0 : warpSums[warp - 1];
    int pos = warpBase + x - cnt;
#pragma unroll
    for (int i = 0; i < 4; i++) {
        if (v[i]) {
            g_idx[b][pos]  = base + i;
            g_bias[b][pos] = -SM_SHIFT;
            pos++;
        }
    }
    __syncthreads();
    int total  = warpSums[31];
    int padded = (total + 63) & ~63;
    for (int j = total + tid; j < padded; j += 1024) {
        g_idx[b][j]  = 0;
        g_bias[b][j] = -3.0e38f;
    }
    if (tid == 0) g_ntiles[b] = padded >> 6;
}

// ---------------- fp16 GEMM (round-14 winner) ----------------
#define HA_STG (64 * 72)
#define HB_STG (128 * 72)
#define GEMM_SMEM_BYTES (3 * (HA_STG + HB_STG) * 2)

template <int MODE>
__global__ void __launch_bounds__(256, 2) gemm_h_kernel(
    const __half* __restrict__ A, const __half* __restrict__ W,
    const float* __restrict__ bias, void* __restrict__ Cv,
    int S, float outScale)
{
    extern __shared__ char smraw[];
    __half* As = (__half*)smraw;
    __half* Bs = As + 3 * HA_STG;

    const int tid  = threadIdx.x;
    const int lane = tid & 31;
    const int warp = tid >> 5;
    const int lq   = lane >> 2;
    const int kq   = lane & 3;
    const int bm   = blockIdx.x * 64;
    const int bn   = blockIdx.y * 128;
    const int wm   = (warp & 1) * 32;
    const int wn   = (warp >> 1) * 32;

    auto issue = [&](int kt, int s) {
#pragma unroll
        for (int p = 0; p < 2; p++) {
            int i   = p * 256 + tid;
            int row = i >> 3;
            int c8  = i & 7;
            cpasync16h(As + s * HA_STG + row * 72 + c8 * 8,
                       A + (size_t)(bm + row) * E_DIM + kt * 64 + c8 * 8);
        }
#pragma unroll
        for (int p = 0; p < 4; p++) {
            int i   = p * 256 + tid;
            int row = i >> 3;
            int c8  = i & 7;
            cpasync16h(Bs + s * HB_STG + row * 72 + c8 * 8,
                       W + (size_t)(bn + row) * E_DIM + kt * 64 + c8 * 8);
        }
        CP_COMMIT();
    };

    float acc[2][4][4];
#pragma unroll
    for (int mt = 0; mt < 2; mt++)
#pragma unroll
        for (int nt = 0; nt < 4; nt++)
#pragma unroll
            for (int r = 0; r < 4; r++) acc[mt][nt][r] = 0.0f;

    const int aOff = (wm + (lane & 15)) * 72 + ((lane >> 4) << 3);
    const int bOff = (wn + (lane & 7) + ((lane & 16) >> 1)) * 72 + (lane & 8);

    issue(0, 0);
    issue(1, 1);

#pragma unroll 1
    for (int kt = 0; kt < 16; kt++) {
        if (kt < 15) { CP_WAIT(1); } else { CP_WAIT(0); }
        __syncthreads();
        if (kt + 2 < 16) issue(kt + 2, (kt + 2) % 3);

        const int st = kt % 3;
        uint32_t aB = (uint32_t)__cvta_generic_to_shared(As + st * HA_STG);
        uint32_t bB = (uint32_t)__cvta_generic_to_shared(Bs + st * HB_STG);

#pragma unroll
        for (int ks = 0; ks < 4; ks++) {
            const int k0 = ks * 16;
            unsigned af[2][4];
            ldsm4(af[0], aB + 2u * (aOff + k0));
            ldsm4(af[1], aB + 2u * (aOff + 16 * 72 + k0));
#pragma unroll
            for (int np = 0; np < 2; np++) {
                unsigned bf[4];
                ldsm4(bf, bB + 2u * (bOff + np * 16 * 72 + k0));
                mma16(acc[0][2 * np],     af[0], bf[0], bf[1]);
                mma16(acc[1][2 * np],     af[1], bf[0], bf[1]);
                mma16(acc[0][2 * np + 1], af[0], bf[2], bf[3]);
                mma16(acc[1][2 * np + 1], af[1], bf[2], bf[3]);
            }
        }
    }

#pragma unroll
    for (int mt = 0; mt < 2; mt++) {
        int rA = bm + wm + mt * 16 + lq;
#pragma unroll
        for (int nt = 0; nt < 4; nt++) {
            int c0 = bn + wn + nt * 8 + 2 * kq;
            float b0 = bias[c0], b1 = bias[c0 + 1];
            float v0 = (acc[mt][nt][0] + b0) * outScale;
            float v1 = (acc[mt][nt][1] + b1) * outScale;
            float v2 = (acc[mt][nt][2] + b0) * outScale;
            float v3 = (acc[mt][nt][3] + b1) * outScale;
            if (MODE == 1) {
                __half* C = (__half*)Cv;
                int bb = rA / S, ss = rA - bb * S;
                int h = c0 >> 6, d = c0 & 63;
                __half2* p0 = (__half2*)(C + (((size_t)bb * NHEAD + h) * S + ss) * HDIM + d);
                *p0 = __float22half2_rn(make_float2(v0, v1));
                int rA2 = rA + 8;
                int bb2 = rA2 / S, ss2 = rA2 - bb2 * S;
                __half2* p1 = (__half2*)(C + (((size_t)bb2 * NHEAD + h) * S + ss2) * HDIM + d);
                *p1 = __float22half2_rn(make_float2(v2, v3));
            } else {
                float* C = (float*)Cv;
                *(float2*)(C + (size_t)rA * E_DIM + c0)       = make_float2(v0, v1);
                *(float2*)(C + (size_t)(rA + 8) * E_DIM + c0) = make_float2(v2, v3);
            }
        }
    }
}

// ---------------- fp16 KV GEMM (compact contiguous A) ----------------
template <bool TRANS>
__global__ void __launch_bounds__(256, 2) gemm_kv_kernel(
    const __half* __restrict__ A, const __half* __restrict__ W,
    const float* __restrict__ bias, __half* __restrict__ C)
{
    const int tile = blockIdx.x;
    const int b    = tile >> 6;
    const int lt   = tile & 63;
    if (lt >= g_ntiles[b]) return;

    extern __shared__ char smraw[];
    __half* As = (__half*)smraw;
    __half* Bs = As + 3 * HA_STG;

    const int tid  = threadIdx.x;
    const int lane = tid & 31;
    const int warp = tid >> 5;
    const int lq   = lane >> 2;
    const int kq   = lane & 3;
    const int bn   = blockIdx.y * 128;
    const int wm   = (warp & 1) * 32;
    const int wn   = (warp >> 1) * 32;

    const __half* Ab = A + ((size_t)b * IDXCAP + lt * 64) * E_DIM;

    auto issue = [&](int kt, int s) {
#pragma unroll
        for (int p = 0; p < 2; p++) {
            int i   = p * 256 + tid;
            int row = i >> 3;
            int c8  = i & 7;
            cpasync16h(As + s * HA_STG + row * 72 + c8 * 8,
                       Ab + (size_t)row * E_DIM + kt * 64 + c8 * 8);
        }
#pragma unroll
        for (int p = 0; p < 4; p++) {
            int i   = p * 256 + tid;
            int row = i >> 3;
            int c8  = i & 7;
            cpasync16h(Bs + s * HB_STG + row * 72 + c8 * 8,
                       W + (size_t)(bn + row) * E_DIM + kt * 64 + c8 * 8);
        }
        CP_COMMIT();
    };

    float acc[2][4][4];
#pragma unroll
    for (int mt = 0; mt < 2; mt++)
#pragma unroll
        for (int nt = 0; nt < 4; nt++)
#pragma unroll
            for (int r = 0; r < 4; r++) acc[mt][nt][r] = 0.0f;

    const int aOff = (wm + (lane & 15)) * 72 + ((lane >> 4) << 3);
    const int bOff = (wn + (lane & 7) + ((lane & 16) >> 1)) * 72 + (lane & 8);

    issue(0, 0);
    issue(1, 1);

#pragma unroll 1
    for (int kt = 0; kt < 16; kt++) {
        if (kt < 15) { CP_WAIT(1); } else { CP_WAIT(0); }
        __syncthreads();
        if (kt + 2 < 16) issue(kt + 2, (kt + 2) % 3);

        const int st = kt % 3;
        uint32_t aB = (uint32_t)__cvta_generic_to_shared(As + st * HA_STG);
        uint32_t bB = (uint32_t)__cvta_generic_to_shared(Bs + st * HB_STG);

#pragma unroll
        for (int ks = 0; ks < 4; ks++) {
            const int k0 = ks * 16;
            unsigned af[2][4];
            ldsm4(af[0], aB + 2u * (aOff + k0));
            ldsm4(af[1], aB + 2u * (aOff + 16 * 72 + k0));
#pragma unroll
            for (int np = 0; np < 2; np++) {
                unsigned bf[4];
                ldsm4(bf, bB + 2u * (bOff + np * 16 * 72 + k0));
                mma16(acc[0][2 * np],     af[0], bf[0], bf[1]);
                mma16(acc[1][2 * np],     af[1], bf[0], bf[1]);
                mma16(acc[0][2 * np + 1], af[0], bf[2], bf[3]);
                mma16(acc[1][2 * np + 1], af[1], bf[2], bf[3]);
            }
        }
    }

#pragma unroll
    for (int mt = 0; mt < 2; mt++) {
        int sRow = lt * 64 + wm + mt * 16 + lq;
#pragma unroll
        for (int nt = 0; nt < 4; nt++) {
            int c0 = bn + wn + nt * 8 + 2 * kq;
            int h = c0 >> 6, d = c0 & 63;
            float b0 = bias[c0], b1 = bias[c0 + 1];
            __half h0 = __float2half_rn(acc[mt][nt][0] + b0);
            __half h1 = __float2half_rn(acc[mt][nt][1] + b1);
            __half h2 = __float2half_rn(acc[mt][nt][2] + b0);
            __half h3 = __float2half_rn(acc[mt][nt][3] + b1);
            if (TRANS) {
                __half* base = C + ((size_t)b * NHEAD + h) * (size_t)HDIM * SEQ_KV;
                base[(size_t)d * SEQ_KV + sRow]           = h0;
                base[(size_t)(d + 1) * SEQ_KV + sRow]     = h1;
                base[(size_t)d * SEQ_KV + sRow + 8]       = h2;
                base[(size_t)(d + 1) * SEQ_KV + sRow + 8] = h3;
            } else {
                __half2* p0 = (__half2*)(C + (((size_t)b * NHEAD + h) * SEQ_KV + sRow) * HDIM + d);
                *p0 = __halves2half2(h0, h1);
                __half2* p1 = (__half2*)(C + (((size_t)b * NHEAD + h) * SEQ_KV + sRow + 8) * HDIM + d);
                *p1 = __halves2half2(h2, h3);
            }
        }
    }
}

// ---------------- fp16 flash attention, split-KV x2 ----------------
// grid (16, 16, 2): qt = x>>1, split = x&1. Unnormalized O + partial l to scratch.
#define HSTR 72
#define QOFF_H 0
#define KOFF_H (128 * HSTR)
#define VOFF_H (KOFF_H + 2 * 64 * HSTR)
#define TOT_H  (VOFF_H + 2 * 64 * HSTR)
#define MOFF_B (TOT_H * 2)
#define ATT_SMEM_BYTES (MOFF_B + 2 * 64 * 4)

__global__ void __launch_bounds__(128, 3) attn_kernel()
{
    extern __shared__ char smraw[];
    __half* smh  = (__half*)smraw;
    float*  mskF = (float*)(smraw + MOFF_B);

    const int tid  = threadIdx.x;
    const int lane = tid & 31;
    const int warp = tid >> 5;
    const int lq   = lane >> 2;
    const int kq   = lane & 3;
    const int qt = blockIdx.x >> 1, split = blockIdx.x & 1;
    const int h = blockIdx.y, b = blockIdx.z;

    const int nt = g_ntiles[b];
    const int m  = (nt - split + 1) >> 1;   // tiles for this split

    const __half* Qg = g_Qp + (((size_t)b * NHEAD + h) * SEQ_Q + qt * 128) * HDIM;
    const __half* Kg = g_Kp + ((size_t)b * NHEAD + h) * SEQ_KV * HDIM;
    const __half* Vg = g_Vp + ((size_t)b * NHEAD + h) * (size_t)HDIM * SEQ_KV;

#pragma unroll
    for (int p = 0; p < 8; p++) {
        int i   = p * 128 + tid;
        int row = i >> 3;
        int c8  = i & 7;
        cpasync16h(smh + QOFF_H + row * HSTR + c8 * 8, Qg + row * HDIM + c8 * 8);
    }
    CP_COMMIT();
    CP_WAIT(0);
    __syncthreads();

    const int r0 = warp * 32;
    unsigned qf[2][4][4];
    {
        uint32_t qB = (uint32_t)__cvta_generic_to_shared(smh + QOFF_H);
        const int qOff = (r0 + (lane & 15)) * HSTR + ((lane >> 4) << 3);
#pragma unroll
        for (int rb = 0; rb < 2; rb++)
#pragma unroll
            for (int ks = 0; ks < 4; ks++)
                ldsm4(qf[rb][ks], qB + 2u * (qOff + rb * 16 * HSTR + ks * 16));
    }
    __syncthreads();

    auto issue = [&](int kt, int s) {
        const __half* kp = Kg + (size_t)kt * 64 * HDIM;
        const __half* vp = Vg + (size_t)kt * 64;
#pragma unroll
        for (int p = 0; p < 4; p++) {
            int i   = p * 128 + tid;
            int row = i >> 3;
            int c8  = i & 7;
            cpasync16h(smh + KOFF_H + s * 64 * HSTR + row * HSTR + c8 * 8,
                       kp + (size_t)row * HDIM + c8 * 8);
            cpasync16h(smh + VOFF_H + s * 64 * HSTR + row * HSTR + c8 * 8,
                       vp + (size_t)row * SEQ_KV + c8 * 8);
        }
        if (tid < 64) mskF[s * 64 + tid] = g_bias[b][kt * 64 + tid];
        CP_COMMIT();
    };

    float o[2][8][4];
#pragma unroll
    for (int rb = 0; rb < 2; rb++)
#pragma unroll
        for (int ntl = 0; ntl < 8; ntl++)
#pragma unroll
            for (int r = 0; r < 4; r++) o[rb][ntl][r] = 0.0f;

    float lAcc[2][2] = {{0.0f, 0.0f}, {0.0f, 0.0f}};

    if (m > 0) issue(split, 0);
    if (m > 1) issue(split + 2, 1);

    const int kvOff = ((lane & 7) + ((lane & 16) >> 1)) * HSTR + (lane & 8);
    const int pOff  = (r0 + (lane & 15)) * HSTR + ((lane >> 4) << 3);

#pragma unroll 1
    for (int it = 0; it < m; it++) {
        if (it + 1 < m) { CP_WAIT(1); } else { CP_WAIT(0); }
        __syncthreads();
        const int s = it & 1;
        const float* msk = mskF + s * 64;
        uint32_t kB = (uint32_t)__cvta_generic_to_shared(smh + KOFF_H + s * 64 * HSTR);
        uint32_t vB = (uint32_t)__cvta_generic_to_shared(smh + VOFF_H + s * 64 * HSTR);
        uint32_t pB = (uint32_t)__cvta_generic_to_shared(smh + QOFF_H);

        float sacc[2][8][4];
#pragma unroll
        for (int rb = 0; rb < 2; rb++)
#pragma unroll
            for (int ntl = 0; ntl < 8; ntl++)
#pragma unroll
                for (int r = 0; r < 4; r++) sacc[rb][ntl][r] = 0.0f;

#pragma unroll
        for (int ks = 0; ks < 4; ks++) {
            const int k0 = ks * 16;
#pragma unroll
            for (int np = 0; np < 4; np++) {
                unsigned kf[4];
                ldsm4(kf, kB + 2u * (kvOff + np * 16 * HSTR + k0));
                mma16(sacc[0][2 * np],     qf[0][ks], kf[0], kf[1]);
                mma16(sacc[1][2 * np],     qf[1][ks], kf[0], kf[1]);
                mma16(sacc[0][2 * np + 1], qf[0][ks], kf[2], kf[3]);
                mma16(sacc[1][2 * np + 1], qf[1][ks], kf[2], kf[3]);
            }
        }

#pragma unroll
        for (int ntl = 0; ntl < 8; ntl++) {
            float m0 = msk[ntl * 8 + 2 * kq];
            float m1 = msk[ntl * 8 + 2 * kq + 1];
#pragma unroll
            for (int rb = 0; rb < 2; rb++) {
                float p0 = __expf(sacc[rb][ntl][0] + m0);
                float p1 = __expf(sacc[rb][ntl][1] + m1);
                float p2 = __expf(sacc[rb][ntl][2] + m0);
                float p3 = __expf(sacc[rb][ntl][3] + m1);
                lAcc[rb][0] += p0 + p1;
                lAcc[rb][1] += p2 + p3;
                int rr = r0 + rb * 16;
                *(__half2*)(smh + QOFF_H + (rr + lq) * HSTR + ntl * 8 + 2 * kq) =
                    __float22half2_rn(make_float2(p0, p1));
                *(__half2*)(smh + QOFF_H + (rr + 8 + lq) * HSTR + ntl * 8 + 2 * kq) =
                    __float22half2_rn(make_float2(p2, p3));
            }
        }
        __syncwarp();

#pragma unroll
        for (int ks = 0; ks < 4; ks++) {
            const int k0 = ks * 16;
            unsigned pf[2][4];
            ldsm4(pf[0], pB + 2u * (pOff + k0));
            ldsm4(pf[1], pB + 2u * (pOff + 16 * HSTR + k0));
#pragma unroll
            for (int np = 0; np < 4; np++) {
                unsigned vf[4];
                ldsm4(vf, vB + 2u * (kvOff + np * 16 * HSTR + k0));
                mma16(o[0][2 * np],     pf[0], vf[0], vf[1]);
                mma16(o[1][2 * np],     pf[1], vf[0], vf[1]);
                mma16(o[0][2 * np + 1], pf[0], vf[2], vf[3]);
                mma16(o[1][2 * np + 1], pf[1], vf[2], vf[3]);
            }
        }
        __syncthreads();
        if (it + 2 < m) issue(split + 2 * (it + 2), s);
    }

#pragma unroll
    for (int rb = 0; rb < 2; rb++)
#pragma unroll
        for (int j = 0; j < 2; j++) {
            lAcc[rb][j] += __shfl_xor_sync(0xffffffffu, lAcc[rb][j], 1);
            lAcc[rb][j] += __shfl_xor_sync(0xffffffffu, lAcc[rb][j], 2);
        }

    // write unnormalized partials
    float* oBase = g_oacc[split] + (((size_t)b * NHEAD + h) * SEQ_Q + qt * 128) * HDIM;
    float* lBase = g_lacc[split] + ((size_t)b * NHEAD + h) * SEQ_Q + qt * 128;
#pragma unroll
    for (int rb = 0; rb < 2; rb++) {
        int rloc = r0 + rb * 16 + lq;
#pragma unroll
        for (int ntl = 0; ntl < 8; ntl++) {
            int c = ntl * 8 + 2 * kq;
            *(float2*)(oBase + (size_t)rloc * HDIM + c) =
                make_float2(o[rb][ntl][0], o[rb][ntl][1]);
            *(float2*)(oBase + (size_t)(rloc + 8) * HDIM + c) =
                make_float2(o[rb][ntl][2], o[rb][ntl][3]);
        }
        if (kq == 0) {
            lBase[rloc]     = lAcc[rb][0];
            lBase[rloc + 8] = lAcc[rb][1];
        }
    }
}

// ---------------- split-KV combine: O = (O0+O1)/(l0+l1) -> fp16 [B,SQ,E] ----------------
__global__ void __launch_bounds__(256) combine_kernel()
{
    int idx = blockIdx.x * 256 + threadIdx.x;     // over B*H*SQ*8 chunks
    int row = idx >> 3;                            // b*H*SQ + h*SQ + sq
    int d   = (idx & 7) * 8;
    float l = g_lacc[0][row] + g_lacc[1][row];
    float r = 1.0f / l;
    const float* o0 = g_oacc[0] + (size_t)row * HDIM + d;
    const float* o1 = g_oacc[1] + (size_t)row * HDIM + d;
    int b  = row >> 14;            // / (NHEAD*SEQ_Q)
    int hh = (row >> 10) & 15;     // / SEQ_Q % NHEAD
    int sq = row & 1023;
    __half2* out = (__half2*)(g_attnh + ((size_t)b * SEQ_Q + sq) * E_DIM + hh * HDIM + d);
#pragma unroll
    for (int j = 0; j < 2; j++) {
        float4 a = ((const float4*)o0)[j];
        float4 c = ((const float4*)o1)[j];
        out[j * 2]     = __float22half2_rn(make_float2((a.x + c.x) * r, (a.y + c.y) * r));
        out[j * 2 + 1] = __float22half2_rn(make_float2((a.z + c.z) * r, (a.w + c.w) * r));
    }
}

// ---------------- residual + LayerNorm ----------------
__global__ void __launch_bounds__(256) ln_kernel(
    const float* __restrict__ query, const float* __restrict__ proj,
    const float* __restrict__ gamma, const float* __restrict__ beta,
    float* __restrict__ out)
{
    __shared__ float rs[8], rs2[8];
    const int row = blockIdx.x, tid = threadIdx.x;
    const int lane = tid & 31, warp = tid >> 5;
    const size_t base = (size_t)row * E_DIM + tid * 4;

    float4 q = *(const float4*)(query + base);
    float4 p = *(const float4*)(proj + base);
    float x0 = q.x + p.x, x1 = q.y + p.y, x2 = q.z + p.z, x3 = q.w + p.w;
    float s  = x0 + x1 + x2 + x3;
    float s2 = x0 * x0 + x1 * x1 + x2 * x2 + x3 * x3;
#pragma unroll
    for (int off = 16; off; off >>= 1) {
        s  += __shfl_xor_sync(0xffffffffu, s, off);
        s2 += __shfl_xor_sync(0xffffffffu, s2, off);
    }
    if (lane == 0) { rs[warp] = s; rs2[warp] = s2; }
    __syncthreads();
    s = 0.0f; s2 = 0.0f;
#pragma unroll
    for (int i = 0; i < 8; i++) { s += rs[i]; s2 += rs2[i]; }

    float mean = s * (1.0f / E_DIM);
    float var  = s2 * (1.0f / E_DIM) - mean * mean;
    float rstd = rsqrtf(var + LN_EPS);

    float4 g  = *(const float4*)(gamma + tid * 4);
    float4 bb = *(const float4*)(beta + tid * 4);
    float4 r;
    r.x = (x0 - mean) * rstd * g.x + bb.x;
    r.y = (x1 - mean) * rstd * g.y + bb.y;
    r.z = (x2 - mean) * rstd * g.z + bb.z;
    r.w = (x3 - mean) * rstd * g.w + bb.w;
    *(float4*)(out + base) = r;
}

// ---------------- launch ----------------
extern "C" void kernel_launch(void* const* d_in, const int* in_sizes, int n_in,
                              void* d_out, int out_size)
{
    const float* query     = (const float*)d_in[0];
    const float* key_value = (const float*)d_in[1];
    const int*   kvmask    = (const int*)d_in[2];
    const float* Wq = (const float*)d_in[3];
    const float* bq = (const float*)d_in[4];
    const float* Wk = (const float*)d_in[5];
    const float* bk = (const float*)d_in[6];
    const float* Wv = (const float*)d_in[7];
    const float* bv = (const float*)d_in[8];
    const float* Wo = (const float*)d_in[9];
    const float* bo = (const float*)d_in[10];
    const float* gamma = (const float*)d_in[11];
    const float* beta  = (const float*)d_in[12];
    float* out = (float*)d_out;

    __half *qh, *wh, *Qp, *Kp, *Vp, *attnh, *kvc;
    float *proj;
    cudaGetSymbolAddress((void**)&qh, g_qh);
    cudaGetSymbolAddress((void**)&wh, g_wh);
    cudaGetSymbolAddress((void**)&Qp, g_Qp);
    cudaGetSymbolAddress((void**)&Kp, g_Kp);
    cudaGetSymbolAddress((void**)&Vp, g_Vp);
    cudaGetSymbolAddress((void**)&attnh, g_attnh);
    cudaGetSymbolAddress((void**)&proj, g_proj);
    cudaGetSymbolAddress((void**)&kvc, g_kvc);

    cudaFuncSetAttribute(gemm_h_kernel<0>,
                         cudaFuncAttributeMaxDynamicSharedMemorySize, GEMM_SMEM_BYTES);
    cudaFuncSetAttribute(gemm_h_kernel<1>,
                         cudaFuncAttributeMaxDynamicSharedMemorySize, GEMM_SMEM_BYTES);
    cudaFuncSetAttribute(gemm_kv_kernel<false>,
                         cudaFuncAttributeMaxDynamicSharedMemorySize, GEMM_SMEM_BYTES);
    cudaFuncSetAttribute(gemm_kv_kernel<true>,
                         cudaFuncAttributeMaxDynamicSharedMemorySize, GEMM_SMEM_BYTES);
    cudaFuncSetAttribute(attn_kernel,
                         cudaFuncAttributeMaxDynamicSharedMemorySize, ATT_SMEM_BYTES);

    // compaction + conversions
    compact_kernel<<<BATCH, 1024>>>(kvmask);
    conv_one<<<BATCH * SEQ_Q * E_DIM / 4 / 1024, 256>>>(query, qh);
    conv_w<<<dim3(E_DIM * E_DIM / 4 / 1024, 4), 256>>>(Wq, Wk, Wv, Wo, wh);
    conv_kvc<<<dim3(SEQ_KV / 8, BATCH), 256>>>(key_value);

    // projections
    gemm_h_kernel<1><<<dim3(BATCH * SEQ_Q / 64, 8), 256, GEMM_SMEM_BYTES>>>(
        qh, wh, bq, Qp, SEQ_Q, 0.125f);
    gemm_kv_kernel<false><<<dim3(BATCH * 64, 8), 256, GEMM_SMEM_BYTES>>>(
        kvc, wh + (size_t)E_DIM * E_DIM, bk, Kp);
    gemm_kv_kernel<true><<<dim3(BATCH * 64, 8), 256, GEMM_SMEM_BYTES>>>(
        kvc, wh + 2 * (size_t)E_DIM * E_DIM, bv, Vp);

    // attention (split-KV x2) + combine
    attn_kernel<<<dim3(SEQ_Q / 128 * 2, NHEAD, BATCH), 128, ATT_SMEM_BYTES>>>();
    combine_kernel<<<BATCH * NHEAD * SEQ_Q * 8 / 256, 256>>>();

    // output projection (fp32 out)
    gemm_h_kernel<0><<<dim3(BATCH * SEQ_Q / 64, 8), 256, GEMM_SMEM_BYTES>>>(
        attnh, wh + 3 * (size_t)E_DIM * E_DIM, bo, proj, SEQ_Q, 1.0f);

    // residual + LN
    ln_kernel<<<BATCH * SEQ_Q, 256>>>(query, proj, gamma, beta, out);
}

// round 16
// speedup vs baseline: 1.0738x; 1.0738x over previous
#include <cuda_runtime.h>
#include <cuda_fp16.h>
#include <cstdint>
#include <cstddef>

#define E_DIM  1024
#define NHEAD  16
#define HDIM   64
#define BATCH  2
#define SEQ_Q  1024
#define SEQ_KV 4096
#define LN_EPS 1e-5f
#define SM_SHIFT 8.0f
#define LOG2E 1.4426950408889634f
#define IDXCAP 4160

// ---------------- scratch (no allocations allowed) ----------------
__device__ __half g_qh  [(size_t)BATCH * SEQ_Q * E_DIM];
__device__ __half g_kvc [(size_t)BATCH * IDXCAP * E_DIM];
__device__ __half g_wh  [(size_t)4 * E_DIM * E_DIM];
__device__ __half g_Qp  [(size_t)BATCH * NHEAD * SEQ_Q * HDIM];
__device__ __half g_Kp  [(size_t)BATCH * NHEAD * SEQ_KV * HDIM];
__device__ __half g_Vp  [(size_t)BATCH * NHEAD * SEQ_KV * HDIM];
__device__ __half g_attnh[(size_t)BATCH * SEQ_Q * E_DIM];
__device__ float  g_proj[(size_t)BATCH * SEQ_Q * E_DIM];
__device__ float  g_oacc[2][(size_t)BATCH * NHEAD * SEQ_Q * HDIM];
__device__ float  g_lacc[2][(size_t)BATCH * NHEAD * SEQ_Q];
__device__ int    g_idx [BATCH][IDXCAP];
__device__ float  g_bias[BATCH][IDXCAP];   // log2e-scaled bias: -SM_SHIFT*LOG2E real / -100 pad
__device__ int    g_ntiles[BATCH];

// ---------------- helpers ----------------
__device__ __forceinline__ void mma16(float* c, const unsigned* a, unsigned b0, unsigned b1) {
    asm volatile(
        "mma.sync.aligned.m16n8k16.row.col.f32.f16.f16.f32 "
        "{%0,%1,%2,%3}, {%4,%5,%6,%7}, {%8,%9}, {%0,%1,%2,%3};\n"
        : "+f"(c[0]), "+f"(c[1]), "+f"(c[2]), "+f"(c[3])
        : "r"(a[0]), "r"(a[1]), "r"(a[2]), "r"(a[3]), "r"(b0), "r"(b1));
}

__device__ __forceinline__ void ldsm4(unsigned* r, uint32_t addr) {
    asm volatile("ldmatrix.sync.aligned.m8n8.x4.shared.b16 {%0,%1,%2,%3}, [%4];"
                 : "=r"(r[0]), "=r"(r[1]), "=r"(r[2]), "=r"(r[3]) : "r"(addr));
}

__device__ __forceinline__ void cpasync16h(const __half* dst, const __half* src) {
    uint32_t d = (uint32_t)__cvta_generic_to_shared(dst);
    asm volatile("cp.async.cg.shared.global [%0], [%1], 16;" :: "r"(d), "l"(src));
}
#define CP_COMMIT() asm volatile("cp.async.commit_group;" ::: "memory")
#define CP_WAIT(n)  asm volatile("cp.async.wait_group %0;" :: "n"(n) : "memory")

// pack two fp32 -> half2, then 2^x on both halves in one MUFU op
__device__ __forceinline__ unsigned exp2h2(float u0, float u1) {
    unsigned h;
    asm("cvt.rn.f16x2.f32 %0, %1, %2;" : "=r"(h) : "f"(u1), "f"(u0));
    asm("ex2.approx.f16x2 %0, %0;" : "+r"(h));
    return h;
}

// ---------------- conversion kernels ----------------
__global__ void __launch_bounds__(256) conv_one(const float* __restrict__ in,
                                                __half* __restrict__ out) {
    int base = blockIdx.x * 1024 + threadIdx.x;
#pragma unroll
    for (int j = 0; j < 4; j++) {
        int i = base + j * 256;
        float4 v = ((const float4*)in)[i];
        __half2* o = (__half2*)out + i * 2;
        o[0] = __float22half2_rn(make_float2(v.x, v.y));
        o[1] = __float22half2_rn(make_float2(v.z, v.w));
    }
}

__global__ void __launch_bounds__(256) conv_w(const float* __restrict__ a,
                                              const float* __restrict__ b,
                                              const float* __restrict__ c,
                                              const float* __restrict__ d,
                                              __half* __restrict__ o) {
    const float* in = (blockIdx.y == 0) ? a : (blockIdx.y == 1) ? b : (blockIdx.y == 2) ? c : d;
    __half* out = o + (size_t)blockIdx.y * E_DIM * E_DIM;
    int base = blockIdx.x * 1024 + threadIdx.x;
#pragma unroll
    for (int j = 0; j < 4; j++) {
        int i = base + j * 256;
        float4 v = ((const float4*)in)[i];
        __half2* op = (__half2*)out + i * 2;
        op[0] = __float22half2_rn(make_float2(v.x, v.y));
        op[1] = __float22half2_rn(make_float2(v.z, v.w));
    }
}

__global__ void __launch_bounds__(256) conv_kvc(const float* __restrict__ kv) {
    const int b = blockIdx.y;
    const int rbase = blockIdx.x * 8;
    if (rbase >= g_ntiles[b] * 64) return;
    const int rloc = threadIdx.x >> 5;
    const int t32  = threadIdx.x & 31;
    const int row  = rbase + rloc;
    const int src  = g_idx[b][row];
    const float4* sp = (const float4*)(kv + ((size_t)b * SEQ_KV + src) * E_DIM) + t32;
    __half2* dp = (__half2*)(g_kvc + ((size_t)b * IDXCAP + row) * E_DIM) + t32 * 2;
#pragma unroll
    for (int j = 0; j < 8; j++) {
        float4 v = sp[j * 32];
        dp[j * 64]     = __float22half2_rn(make_float2(v.x, v.y));
        dp[j * 64 + 1] = __float22half2_rn(make_float2(v.z, v.w));
    }
}

// ---------------- mask compaction ----------------
__global__ void __launch_bounds__(1024) compact_kernel(const int* __restrict__ mask) {
    const int b   = blockIdx.x;
    const int tid = threadIdx.x;
    const int lane = tid & 31, warp = tid >> 5;
    const int* m = mask + (size_t)b * SEQ_KV;
    __shared__ int warpSums[32];

    int v[4];
    int base = tid * 4;
    int cnt = 0;
#pragma unroll
    for (int i = 0; i < 4; i++) { v[i] = (m[base + i] != 0); cnt += v[i]; }

    int x = cnt;
#pragma unroll
    for (int off = 1; off < 32; off <<= 1) {
        int y = __shfl_up_sync(0xffffffffu, x, off);
        if (lane >= off) x += y;
    }
    if (lane == 31) warpSums[warp] = x;
    __syncthreads();
    if (warp == 0) {
        int wsum = warpSums[lane];
#pragma unroll
        for (int off = 1; off < 32; off <<= 1) {
            int y = __shfl_up_sync(0xffffffffu, wsum, off);
            if (lane >= off) wsum += y;
        }
        warpSums[lane] = wsum;
    }
    __syncthreads();
    int warpBase = (warp == 0) ? 0 : warpSums[warp - 1];
    int pos = warpBase + x - cnt;
#pragma unroll
    for (int i = 0; i < 4; i++) {
        if (v[i]) {
            g_idx[b][pos]  = base + i;
            g_bias[b][pos] = -SM_SHIFT * LOG2E;
            pos++;
        }
    }
    __syncthreads();
    int total  = warpSums[31];
    int padded = (total + 63) & ~63;
    for (int j = total + tid; j < padded; j += 1024) {
        g_idx[b][j]  = 0;
        g_bias[b][j] = -100.0f;
    }
    if (tid == 0) g_ntiles[b] = padded >> 6;
}

// ---------------- fp16 GEMM (round-14 winner) ----------------
#define HA_STG (64 * 72)
#define HB_STG (128 * 72)
#define GEMM_SMEM_BYTES (3 * (HA_STG + HB_STG) * 2)

template <int MODE>
__global__ void __launch_bounds__(256, 2) gemm_h_kernel(
    const __half* __restrict__ A, const __half* __restrict__ W,
    const float* __restrict__ bias, void* __restrict__ Cv,
    int S, float outScale)
{
    extern __shared__ char smraw[];
    __half* As = (__half*)smraw;
    __half* Bs = As + 3 * HA_STG;

    const int tid  = threadIdx.x;
    const int lane = tid & 31;
    const int warp = tid >> 5;
    const int lq   = lane >> 2;
    const int kq   = lane & 3;
    const int bm   = blockIdx.x * 64;
    const int bn   = blockIdx.y * 128;
    const int wm   = (warp & 1) * 32;
    const int wn   = (warp >> 1) * 32;

    auto issue = [&](int kt, int s) {
#pragma unroll
        for (int p = 0; p < 2; p++) {
            int i   = p * 256 + tid;
            int row = i >> 3;
            int c8  = i & 7;
            cpasync16h(As + s * HA_STG + row * 72 + c8 * 8,
                       A + (size_t)(bm + row) * E_DIM + kt * 64 + c8 * 8);
        }
#pragma unroll
        for (int p = 0; p < 4; p++) {
            int i   = p * 256 + tid;
            int row = i >> 3;
            int c8  = i & 7;
            cpasync16h(Bs + s * HB_STG + row * 72 + c8 * 8,
                       W + (size_t)(bn + row) * E_DIM + kt * 64 + c8 * 8);
        }
        CP_COMMIT();
    };

    float acc[2][4][4];
#pragma unroll
    for (int mt = 0; mt < 2; mt++)
#pragma unroll
        for (int nt = 0; nt < 4; nt++)
#pragma unroll
            for (int r = 0; r < 4; r++) acc[mt][nt][r] = 0.0f;

    const int aOff = (wm + (lane & 15)) * 72 + ((lane >> 4) << 3);
    const int bOff = (wn + (lane & 7) + ((lane & 16) >> 1)) * 72 + (lane & 8);

    issue(0, 0);
    issue(1, 1);

#pragma unroll 1
    for (int kt = 0; kt < 16; kt++) {
        if (kt < 15) { CP_WAIT(1); } else { CP_WAIT(0); }
        __syncthreads();
        if (kt + 2 < 16) issue(kt + 2, (kt + 2) % 3);

        const int st = kt % 3;
        uint32_t aB = (uint32_t)__cvta_generic_to_shared(As + st * HA_STG);
        uint32_t bB = (uint32_t)__cvta_generic_to_shared(Bs + st * HB_STG);

#pragma unroll
        for (int ks = 0; ks < 4; ks++) {
            const int k0 = ks * 16;
            unsigned af[2][4];
            ldsm4(af[0], aB + 2u * (aOff + k0));
            ldsm4(af[1], aB + 2u * (aOff + 16 * 72 + k0));
#pragma unroll
            for (int np = 0; np < 2; np++) {
                unsigned bf[4];
                ldsm4(bf, bB + 2u * (bOff + np * 16 * 72 + k0));
                mma16(acc[0][2 * np],     af[0], bf[0], bf[1]);
                mma16(acc[1][2 * np],     af[1], bf[0], bf[1]);
                mma16(acc[0][2 * np + 1], af[0], bf[2], bf[3]);
                mma16(acc[1][2 * np + 1], af[1], bf[2], bf[3]);
            }
        }
    }

#pragma unroll
    for (int mt = 0; mt < 2; mt++) {
        int rA = bm + wm + mt * 16 + lq;
#pragma unroll
        for (int nt = 0; nt < 4; nt++) {
            int c0 = bn + wn + nt * 8 + 2 * kq;
            float b0 = bias[c0], b1 = bias[c0 + 1];
            float v0 = (acc[mt][nt][0] + b0) * outScale;
            float v1 = (acc[mt][nt][1] + b1) * outScale;
            float v2 = (acc[mt][nt][2] + b0) * outScale;
            float v3 = (acc[mt][nt][3] + b1) * outScale;
            if (MODE == 1) {
                __half* C = (__half*)Cv;
                int bb = rA / S, ss = rA - bb * S;
                int h = c0 >> 6, d = c0 & 63;
                __half2* p0 = (__half2*)(C + (((size_t)bb * NHEAD + h) * S + ss) * HDIM + d);
                *p0 = __float22half2_rn(make_float2(v0, v1));
                int rA2 = rA + 8;
                int bb2 = rA2 / S, ss2 = rA2 - bb2 * S;
                __half2* p1 = (__half2*)(C + (((size_t)bb2 * NHEAD + h) * S + ss2) * HDIM + d);
                *p1 = __float22half2_rn(make_float2(v2, v3));
            } else {
                float* C = (float*)Cv;
                *(float2*)(C + (size_t)rA * E_DIM + c0)       = make_float2(v0, v1);
                *(float2*)(C + (size_t)(rA + 8) * E_DIM + c0) = make_float2(v2, v3);
            }
        }
    }
}

// ---------------- merged K+V GEMM (compact contiguous A, one launch) ----------------
// grid.x = B*64 row-tiles, grid.y = 16: y<8 -> K (Wk,bk), y>=8 -> V transposed (Wv,bv).
__global__ void __launch_bounds__(256, 2) gemm_kv_kernel(
    const __half* __restrict__ A,
    const __half* __restrict__ Wk, const __half* __restrict__ Wv,
    const float* __restrict__ bk, const float* __restrict__ bv,
    __half* __restrict__ Kp, __half* __restrict__ Vp)
{
    const int tile = blockIdx.x;
    const int b    = tile >> 6;
    const int lt   = tile & 63;
    if (lt >= g_ntiles[b]) return;

    const bool isV = blockIdx.y >= 8;
    const __half* W   = isV ? Wv : Wk;
    const float* bias = isV ? bv : bk;
    const int bn      = (blockIdx.y & 7) * 128;

    extern __shared__ char smraw[];
    __half* As = (__half*)smraw;
    __half* Bs = As + 3 * HA_STG;

    const int tid  = threadIdx.x;
    const int lane = tid & 31;
    const int warp = tid >> 5;
    const int lq   = lane >> 2;
    const int kq   = lane & 3;
    const int wm   = (warp & 1) * 32;
    const int wn   = (warp >> 1) * 32;

    const __half* Ab = A + ((size_t)b * IDXCAP + lt * 64) * E_DIM;

    auto issue = [&](int kt, int s) {
#pragma unroll
        for (int p = 0; p < 2; p++) {
            int i   = p * 256 + tid;
            int row = i >> 3;
            int c8  = i & 7;
            cpasync16h(As + s * HA_STG + row * 72 + c8 * 8,
                       Ab + (size_t)row * E_DIM + kt * 64 + c8 * 8);
        }
#pragma unroll
        for (int p = 0; p < 4; p++) {
            int i   = p * 256 + tid;
            int row = i >> 3;
            int c8  = i & 7;
            cpasync16h(Bs + s * HB_STG + row * 72 + c8 * 8,
                       W + (size_t)(bn + row) * E_DIM + kt * 64 + c8 * 8);
        }
        CP_COMMIT();
    };

    float acc[2][4][4];
#pragma unroll
    for (int mt = 0; mt < 2; mt++)
#pragma unroll
        for (int nt = 0; nt < 4; nt++)
#pragma unroll
            for (int r = 0; r < 4; r++) acc[mt][nt][r] = 0.0f;

    const int aOff = (wm + (lane & 15)) * 72 + ((lane >> 4) << 3);
    const int bOff = (wn + (lane & 7) + ((lane & 16) >> 1)) * 72 + (lane & 8);

    issue(0, 0);
    issue(1, 1);

#pragma unroll 1
    for (int kt = 0; kt < 16; kt++) {
        if (kt < 15) { CP_WAIT(1); } else { CP_WAIT(0); }
        __syncthreads();
        if (kt + 2 < 16) issue(kt + 2, (kt + 2) % 3);

        const int st = kt % 3;
        uint32_t aB = (uint32_t)__cvta_generic_to_shared(As + st * HA_STG);
        uint32_t bB = (uint32_t)__cvta_generic_to_shared(Bs + st * HB_STG);

#pragma unroll
        for (int ks = 0; ks < 4; ks++) {
            const int k0 = ks * 16;
            unsigned af[2][4];
            ldsm4(af[0], aB + 2u * (aOff + k0));
            ldsm4(af[1], aB + 2u * (aOff + 16 * 72 + k0));
#pragma unroll
            for (int np = 0; np < 2; np++) {
                unsigned bf[4];
                ldsm4(bf, bB + 2u * (bOff + np * 16 * 72 + k0));
                mma16(acc[0][2 * np],     af[0], bf[0], bf[1]);
                mma16(acc[1][2 * np],     af[1], bf[0], bf[1]);
                mma16(acc[0][2 * np + 1], af[0], bf[2], bf[3]);
                mma16(acc[1][2 * np + 1], af[1], bf[2], bf[3]);
            }
        }
    }

#pragma unroll
    for (int mt = 0; mt < 2; mt++) {
        int sRow = lt * 64 + wm + mt * 16 + lq;
#pragma unroll
        for (int nt = 0; nt < 4; nt++) {
            int c0 = bn + wn + nt * 8 + 2 * kq;
            int h = c0 >> 6, d = c0 & 63;
            float b0 = bias[c0], b1 = bias[c0 + 1];
            __half h0 = __float2half_rn(acc[mt][nt][0] + b0);
            __half h1 = __float2half_rn(acc[mt][nt][1] + b1);
            __half h2 = __float2half_rn(acc[mt][nt][2] + b0);
            __half h3 = __float2half_rn(acc[mt][nt][3] + b1);
            if (isV) {
                __half* base = Vp + ((size_t)b * NHEAD + h) * (size_t)HDIM * SEQ_KV;
                base[(size_t)d * SEQ_KV + sRow]           = h0;
                base[(size_t)(d + 1) * SEQ_KV + sRow]     = h1;
                base[(size_t)d * SEQ_KV + sRow + 8]       = h2;
                base[(size_t)(d + 1) * SEQ_KV + sRow + 8] = h3;
            } else {
                __half2* p0 = (__half2*)(Kp + (((size_t)b * NHEAD + h) * SEQ_KV + sRow) * HDIM + d);
                *p0 = __halves2half2(h0, h1);
                __half2* p1 = (__half2*)(Kp + (((size_t)b * NHEAD + h) * SEQ_KV + sRow + 8) * HDIM + d);
                *p1 = __halves2half2(h2, h3);
            }
        }
    }
}

// ---------------- fp16 flash attention, split-KV x2, exp2.f16x2, l-via-mma ----------------
// V tile has 80 rows: rows 0..63 = V data (d-major), row 64 = ones (l column), 65..71 = 0.
#define HSTR 72
#define V2ROWS 80
#define QOFF_H 0
#define KOFF_H (128 * HSTR)
#define VOFF_H (KOFF_H + 2 * 64 * HSTR)
#define TOT_H  (VOFF_H + 2 * V2ROWS * HSTR)
#define MOFF_B (TOT_H * 2)
#define ATT_SMEM_BYTES (MOFF_B + 2 * 64 * 4)

__global__ void __launch_bounds__(128, 3) attn_kernel()
{
    extern __shared__ char smraw[];
    __half* smh  = (__half*)smraw;
    float*  mskF = (float*)(smraw + MOFF_B);

    const int tid  = threadIdx.x;
    const int lane = tid & 31;
    const int warp = tid >> 5;
    const int lq   = lane >> 2;
    const int kq   = lane & 3;
    const int qt = blockIdx.x >> 1, split = blockIdx.x & 1;
    const int h = blockIdx.y, b = blockIdx.z;

    const int nt = g_ntiles[b];
    const int m  = (nt - split + 1) >> 1;

    const __half* Qg = g_Qp + (((size_t)b * NHEAD + h) * SEQ_Q + qt * 128) * HDIM;
    const __half* Kg = g_Kp + ((size_t)b * NHEAD + h) * SEQ_KV * HDIM;
    const __half* Vg = g_Vp + ((size_t)b * NHEAD + h) * (size_t)HDIM * SEQ_KV;

#pragma unroll
    for (int p = 0; p < 8; p++) {
        int i   = p * 128 + tid;
        int row = i >> 3;
        int c8  = i & 7;
        cpasync16h(smh + QOFF_H + row * HSTR + c8 * 8, Qg + row * HDIM + c8 * 8);
    }
    CP_COMMIT();
    CP_WAIT(0);
    __syncthreads();

    const int r0 = warp * 32;
    unsigned qf[2][4][4];
    {
        uint32_t qB = (uint32_t)__cvta_generic_to_shared(smh + QOFF_H);
        const int qOff = (r0 + (lane & 15)) * HSTR + ((lane >> 4) << 3);
#pragma unroll
        for (int rb = 0; rb < 2; rb++)
#pragma unroll
            for (int ks = 0; ks < 4; ks++)
                ldsm4(qf[rb][ks], qB + 2u * (qOff + rb * 16 * HSTR + ks * 16));
    }
    __syncthreads();

    // init V pad rows (64 = ones for l-column, 65..71 = zero) in both stage buffers
    {
        const __half one  = __float2half_rn(1.0f);
        const __half zero = __float2half_rn(0.0f);
        for (int i = tid; i < 2 * 8 * HSTR; i += 128) {
            int s  = i / (8 * HSTR);
            int rr = (i % (8 * HSTR)) / HSTR;
            int cc = i % HSTR;
            smh[VOFF_H + s * V2ROWS * HSTR + (64 + rr) * HSTR + cc] = (rr == 0) ? one : zero;
        }
    }

    auto issue = [&](int kt, int s) {
        const __half* kp = Kg + (size_t)kt * 64 * HDIM;
        const __half* vp = Vg + (size_t)kt * 64;
#pragma unroll
        for (int p = 0; p < 4; p++) {
            int i   = p * 128 + tid;
            int row = i >> 3;
            int c8  = i & 7;
            cpasync16h(smh + KOFF_H + s * 64 * HSTR + row * HSTR + c8 * 8,
                       kp + (size_t)row * HDIM + c8 * 8);
            cpasync16h(smh + VOFF_H + s * V2ROWS * HSTR + row * HSTR + c8 * 8,
                       vp + (size_t)row * SEQ_KV + c8 * 8);
        }
        if (tid < 64) mskF[s * 64 + tid] = g_bias[b][kt * 64 + tid];
        CP_COMMIT();
    };

    float o[2][9][4];
#pragma unroll
    for (int rb = 0; rb < 2; rb++)
#pragma unroll
        for (int ntl = 0; ntl < 9; ntl++)
#pragma unroll
            for (int r = 0; r < 4; r++) o[rb][ntl][r] = 0.0f;

    if (m > 0) issue(split, 0);
    if (m > 1) issue(split + 2, 1);

    const int kvOff = ((lane & 7) + ((lane & 16) >> 1)) * HSTR + (lane & 8);
    const int pOff  = (r0 + (lane & 15)) * HSTR + ((lane >> 4) << 3);

#pragma unroll 1
    for (int it = 0; it < m; it++) {
        if (it + 1 < m) { CP_WAIT(1); } else { CP_WAIT(0); }
        __syncthreads();
        const int s = it & 1;
        const float* msk = mskF + s * 64;
        uint32_t kB = (uint32_t)__cvta_generic_to_shared(smh + KOFF_H + s * 64 * HSTR);
        uint32_t vB = (uint32_t)__cvta_generic_to_shared(smh + VOFF_H + s * V2ROWS * HSTR);
        uint32_t pB = (uint32_t)__cvta_generic_to_shared(smh + QOFF_H);

        float sacc[2][8][4];
#pragma unroll
        for (int rb = 0; rb < 2; rb++)
#pragma unroll
            for (int ntl = 0; ntl < 8; ntl++)
#pragma unroll
                for (int r = 0; r < 4; r++) sacc[rb][ntl][r] = 0.0f;

#pragma unroll
        for (int ks = 0; ks < 4; ks++) {
            const int k0 = ks * 16;
#pragma unroll
            for (int np = 0; np < 4; np++) {
                unsigned kf[4];
                ldsm4(kf, kB + 2u * (kvOff + np * 16 * HSTR + k0));
                mma16(sacc[0][2 * np],     qf[0][ks], kf[0], kf[1]);
                mma16(sacc[1][2 * np],     qf[1][ks], kf[0], kf[1]);
                mma16(sacc[0][2 * np + 1], qf[0][ks], kf[2], kf[3]);
                mma16(sacc[1][2 * np + 1], qf[1][ks], kf[2], kf[3]);
            }
        }

        // P = 2^(S*log2e + bias)  (one MUFU per two elements, stored straight to smem)
#pragma unroll
        for (int ntl = 0; ntl < 8; ntl++) {
            float m0 = msk[ntl * 8 + 2 * kq];
            float m1 = msk[ntl * 8 + 2 * kq + 1];
#pragma unroll
            for (int rb = 0; rb < 2; rb++) {
                float u0 = fmaf(sacc[rb][ntl][0], LOG2E, m0);
                float u1 = fmaf(sacc[rb][ntl][1], LOG2E, m1);
                float u2 = fmaf(sacc[rb][ntl][2], LOG2E, m0);
                float u3 = fmaf(sacc[rb][ntl][3], LOG2E, m1);
                int rr = r0 + rb * 16;
                *(unsigned*)(smh + QOFF_H + (rr + lq) * HSTR + ntl * 8 + 2 * kq)     = exp2h2(u0, u1);
                *(unsigned*)(smh + QOFF_H + (rr + 8 + lq) * HSTR + ntl * 8 + 2 * kq) = exp2h2(u2, u3);
            }
        }
        __syncwarp();

        // O += P V ; extra n-group (cols 64..71, ones row) accumulates l = sum(P)
#pragma unroll
        for (int ks = 0; ks < 4; ks++) {
            const int k0 = ks * 16;
            unsigned pf[2][4];
            ldsm4(pf[0], pB + 2u * (pOff + k0));
            ldsm4(pf[1], pB + 2u * (pOff + 16 * HSTR + k0));
#pragma unroll
            for (int np = 0; np < 4; np++) {
                unsigned vf[4];
                ldsm4(vf, vB + 2u * (kvOff + np * 16 * HSTR + k0));
                mma16(o[0][2 * np],     pf[0], vf[0], vf[1]);
                mma16(o[1][2 * np],     pf[1], vf[0], vf[1]);
                mma16(o[0][2 * np + 1], pf[0], vf[2], vf[3]);
                mma16(o[1][2 * np + 1], pf[1], vf[2], vf[3]);
            }
            {
                unsigned vf[4];
                ldsm4(vf, vB + 2u * (kvOff + 4 * 16 * HSTR + k0));
                mma16(o[0][8], pf[0], vf[0], vf[1]);
                mma16(o[1][8], pf[1], vf[0], vf[1]);
            }
        }
        __syncthreads();
        if (it + 2 < m) issue(split + 2 * (it + 2), s);
    }

    // write unnormalized partials; l lives in o[rb][8][0]/[2] on kq==0 threads
    float* oBase = g_oacc[split] + (((size_t)b * NHEAD + h) * SEQ_Q + qt * 128) * HDIM;
    float* lBase = g_lacc[split] + ((size_t)b * NHEAD + h) * SEQ_Q + qt * 128;
#pragma unroll
    for (int rb = 0; rb < 2; rb++) {
        int rloc = r0 + rb * 16 + lq;
#pragma unroll
        for (int ntl = 0; ntl < 8; ntl++) {
            int c = ntl * 8 + 2 * kq;
            *(float2*)(oBase + (size_t)rloc * HDIM + c) =
                make_float2(o[rb][ntl][0], o[rb][ntl][1]);
            *(float2*)(oBase + (size_t)(rloc + 8) * HDIM + c) =
                make_float2(o[rb][ntl][2], o[rb][ntl][3]);
        }
        if (kq == 0) {
            lBase[rloc]     = o[rb][8][0];
            lBase[rloc + 8] = o[rb][8][2];
        }
    }
}

// ---------------- split-KV combine: O = (O0+O1)/(l0+l1) -> fp16 [B,SQ,E] ----------------
__global__ void __launch_bounds__(256) combine_kernel()
{
    int idx = blockIdx.x * 256 + threadIdx.x;
    int row = idx >> 3;
    int d   = (idx & 7) * 8;
    float l = g_lacc[0][row] + g_lacc[1][row];
    float r = 1.0f / l;
    const float* o0 = g_oacc[0] + (size_t)row * HDIM + d;
    const float* o1 = g_oacc[1] + (size_t)row * HDIM + d;
    int b  = row >> 14;
    int hh = (row >> 10) & 15;
    int sq = row & 1023;
    __half2* out = (__half2*)(g_attnh + ((size_t)b * SEQ_Q + sq) * E_DIM + hh * HDIM + d);
#pragma unroll
    for (int j = 0; j < 2; j++) {
        float4 a = ((const float4*)o0)[j];
        float4 c = ((const float4*)o1)[j];
        out[j * 2]     = __float22half2_rn(make_float2((a.x + c.x) * r, (a.y + c.y) * r));
        out[j * 2 + 1] = __float22half2_rn(make_float2((a.z + c.z) * r, (a.w + c.w) * r));
    }
}

// ---------------- residual + LayerNorm ----------------
__global__ void __launch_bounds__(256) ln_kernel(
    const float* __restrict__ query, const float* __restrict__ proj,
    const float* __restrict__ gamma, const float* __restrict__ beta,
    float* __restrict__ out)
{
    __shared__ float rs[8], rs2[8];
    const int row = blockIdx.x, tid = threadIdx.x;
    const int lane = tid & 31, warp = tid >> 5;
    const size_t base = (size_t)row * E_DIM + tid * 4;

    float4 q = *(const float4*)(query + base);
    float4 p = *(const float4*)(proj + base);
    float x0 = q.x + p.x, x1 = q.y + p.y, x2 = q.z + p.z, x3 = q.w + p.w;
    float s  = x0 + x1 + x2 + x3;
    float s2 = x0 * x0 + x1 * x1 + x2 * x2 + x3 * x3;
#pragma unroll
    for (int off = 16; off; off >>= 1) {
        s  += __shfl_xor_sync(0xffffffffu, s, off);
        s2 += __shfl_xor_sync(0xffffffffu, s2, off);
    }
    if (lane == 0) { rs[warp] = s; rs2[warp] = s2; }
    __syncthreads();
    s = 0.0f; s2 = 0.0f;
#pragma unroll
    for (int i = 0; i < 8; i++) { s += rs[i]; s2 += rs2[i]; }

    float mean = s * (1.0f / E_DIM);
    float var  = s2 * (1.0f / E_DIM) - mean * mean;
    float rstd = rsqrtf(var + LN_EPS);

    float4 g  = *(const float4*)(gamma + tid * 4);
    float4 bb = *(const float4*)(beta + tid * 4);
    float4 r;
    r.x = (x0 - mean) * rstd * g.x + bb.x;
    r.y = (x1 - mean) * rstd * g.y + bb.y;
    r.z = (x2 - mean) * rstd * g.z + bb.z;
    r.w = (x3 - mean) * rstd * g.w + bb.w;
    *(float4*)(out + base) = r;
}

// ---------------- launch ----------------
extern "C" void kernel_launch(void* const* d_in, const int* in_sizes, int n_in,
                              void* d_out, int out_size)
{
    const float* query     = (const float*)d_in[0];
    const float* key_value = (const float*)d_in[1];
    const int*   kvmask    = (const int*)d_in[2];
    const float* Wq = (const float*)d_in[3];
    const float* bq = (const float*)d_in[4];
    const float* Wk = (const float*)d_in[5];
    const float* bk = (const float*)d_in[6];
    const float* Wv = (const float*)d_in[7];
    const float* bv = (const float*)d_in[8];
    const float* Wo = (const float*)d_in[9];
    const float* bo = (const float*)d_in[10];
    const float* gamma = (const float*)d_in[11];
    const float* beta  = (const float*)d_in[12];
    float* out = (float*)d_out;

    __half *qh, *wh, *Qp, *Kp, *Vp, *attnh, *kvc;
    float *proj;
    cudaGetSymbolAddress((void**)&qh, g_qh);
    cudaGetSymbolAddress((void**)&wh, g_wh);
    cudaGetSymbolAddress((void**)&Qp, g_Qp);
    cudaGetSymbolAddress((void**)&Kp, g_Kp);
    cudaGetSymbolAddress((void**)&Vp, g_Vp);
    cudaGetSymbolAddress((void**)&attnh, g_attnh);
    cudaGetSymbolAddress((void**)&proj, g_proj);
    cudaGetSymbolAddress((void**)&kvc, g_kvc);

    cudaFuncSetAttribute(gemm_h_kernel<0>,
                         cudaFuncAttributeMaxDynamicSharedMemorySize, GEMM_SMEM_BYTES);
    cudaFuncSetAttribute(gemm_h_kernel<1>,
                         cudaFuncAttributeMaxDynamicSharedMemorySize, GEMM_SMEM_BYTES);
    cudaFuncSetAttribute(gemm_kv_kernel,
                         cudaFuncAttributeMaxDynamicSharedMemorySize, GEMM_SMEM_BYTES);
    cudaFuncSetAttribute(attn_kernel,
                         cudaFuncAttributeMaxDynamicSharedMemorySize, ATT_SMEM_BYTES);

    // compaction + conversions
    compact_kernel<<<BATCH, 1024>>>(kvmask);
    conv_one<<<BATCH * SEQ_Q * E_DIM / 4 / 1024, 256>>>(query, qh);
    conv_w<<<dim3(E_DIM * E_DIM / 4 / 1024, 4), 256>>>(Wq, Wk, Wv, Wo, wh);
    conv_kvc<<<dim3(SEQ_KV / 8, BATCH), 256>>>(key_value);

    // projections
    gemm_h_kernel<1><<<dim3(BATCH * SEQ_Q / 64, 8), 256, GEMM_SMEM_BYTES>>>(
        qh, wh, bq, Qp, SEQ_Q, 0.125f);
    gemm_kv_kernel<<<dim3(BATCH * 64, 16), 256, GEMM_SMEM_BYTES>>>(
        kvc, wh + (size_t)E_DIM * E_DIM, wh + 2 * (size_t)E_DIM * E_DIM, bk, bv, Kp, Vp);

    // attention (split-KV x2) + combine
    attn_kernel<<<dim3(SEQ_Q / 128 * 2, NHEAD, BATCH), 128, ATT_SMEM_BYTES>>>();
    combine_kernel<<<BATCH * NHEAD * SEQ_Q * 8 / 256, 256>>>();

    // output projection (fp32 out)
    gemm_h_kernel<0><<<dim3(BATCH * SEQ_Q / 64, 8), 256, GEMM_SMEM_BYTES>>>(
        attnh, wh + 3 * (size_t)E_DIM * E_DIM, bo, proj, SEQ_Q, 1.0f);

    // residual + LN
    ln_kernel<<<BATCH * SEQ_Q, 256>>>(query, proj, gamma, beta, out);
}

// round 17
// speedup vs baseline: 1.1452x; 1.0665x over previous
#include <cuda_runtime.h>
#include <cuda_fp16.h>
#include <cstdint>
#include <cstddef>

#define E_DIM  1024
#define NHEAD  16
#define HDIM   64
#define BATCH  2
#define SEQ_Q  1024
#define SEQ_KV 4096
#define LN_EPS 1e-5f
#define SM_SHIFT 8.0f
#define LOG2E 1.4426950408889634f
#define IDXCAP 4160

// ---------------- scratch (no allocations allowed) ----------------
__device__ __half g_qh  [(size_t)BATCH * SEQ_Q * E_DIM];
__device__ __half g_kvc [(size_t)BATCH * IDXCAP * E_DIM];
__device__ __half g_wh  [(size_t)4 * E_DIM * E_DIM];
__device__ __half g_Qp  [(size_t)BATCH * NHEAD * SEQ_Q * HDIM];
__device__ __half g_Kp  [(size_t)BATCH * NHEAD * SEQ_KV * HDIM];
__device__ __half g_Vp  [(size_t)BATCH * NHEAD * SEQ_KV * HDIM];
__device__ __half g_attnh[(size_t)BATCH * SEQ_Q * E_DIM];
__device__ float  g_proj[(size_t)BATCH * SEQ_Q * E_DIM];
__device__ int    g_idx [BATCH][IDXCAP];
__device__ float  g_bias[BATCH][IDXCAP];   // log2e-scaled: -SM_SHIFT*LOG2E real / -100 pad
__device__ int    g_ntiles[BATCH];

// ---------------- helpers ----------------
__device__ __forceinline__ void mma16(float* c, const unsigned* a, unsigned b0, unsigned b1) {
    asm volatile(
        "mma.sync.aligned.m16n8k16.row.col.f32.f16.f16.f32 "
        "{%0,%1,%2,%3}, {%4,%5,%6,%7}, {%8,%9}, {%0,%1,%2,%3};\n"
        : "+f"(c[0]), "+f"(c[1]), "+f"(c[2]), "+f"(c[3])
        : "r"(a[0]), "r"(a[1]), "r"(a[2]), "r"(a[3]), "r"(b0), "r"(b1));
}

__device__ __forceinline__ void ldsm4(unsigned* r, uint32_t addr) {
    asm volatile("ldmatrix.sync.aligned.m8n8.x4.shared.b16 {%0,%1,%2,%3}, [%4];"
                 : "=r"(r[0]), "=r"(r[1]), "=r"(r[2]), "=r"(r[3]) : "r"(addr));
}

__device__ __forceinline__ void cpasync16h(const __half* dst, const __half* src) {
    uint32_t d = (uint32_t)__cvta_generic_to_shared(dst);
    asm volatile("cp.async.cg.shared.global [%0], [%1], 16;" :: "r"(d), "l"(src));
}
#define CP_COMMIT() asm volatile("cp.async.commit_group;" ::: "memory")
#define CP_WAIT(n)  asm volatile("cp.async.wait_group %0;" :: "n"(n) : "memory")

__device__ __forceinline__ unsigned exp2h2(float u0, float u1) {
    unsigned h;
    asm("cvt.rn.f16x2.f32 %0, %1, %2;" : "=r"(h) : "f"(u1), "f"(u0));
    asm("ex2.approx.f16x2 %0, %0;" : "+r"(h));
    return h;
}

// ---------------- conversion kernels ----------------
__global__ void __launch_bounds__(256) conv_one(const float* __restrict__ in,
                                                __half* __restrict__ out) {
    int base = blockIdx.x * 1024 + threadIdx.x;
#pragma unroll
    for (int j = 0; j < 4; j++) {
        int i = base + j * 256;
        float4 v = ((const float4*)in)[i];
        __half2* o = (__half2*)out + i * 2;
        o[0] = __float22half2_rn(make_float2(v.x, v.y));
        o[1] = __float22half2_rn(make_float2(v.z, v.w));
    }
}

__global__ void __launch_bounds__(256) conv_w(const float* __restrict__ a,
                                              const float* __restrict__ b,
                                              const float* __restrict__ c,
                                              const float* __restrict__ d,
                                              __half* __restrict__ o) {
    const float* in = (blockIdx.y == 0) ? a : (blockIdx.y == 1) ? b : (blockIdx.y == 2) ? c : d;
    __half* out = o + (size_t)blockIdx.y * E_DIM * E_DIM;
    int base = blockIdx.x * 1024 + threadIdx.x;
#pragma unroll
    for (int j = 0; j < 4; j++) {
        int i = base + j * 256;
        float4 v = ((const float4*)in)[i];
        __half2* op = (__half2*)out + i * 2;
        op[0] = __float22half2_rn(make_float2(v.x, v.y));
        op[1] = __float22half2_rn(make_float2(v.z, v.w));
    }
}

__global__ void __launch_bounds__(256) conv_kvc(const float* __restrict__ kv) {
    const int b = blockIdx.y;
    const int rbase = blockIdx.x * 8;
    if (rbase >= g_ntiles[b] * 64) return;
    const int rloc = threadIdx.x >> 5;
    const int t32  = threadIdx.x & 31;
    const int row  = rbase + rloc;
    const int src  = g_idx[b][row];
    const float4* sp = (const float4*)(kv + ((size_t)b * SEQ_KV + src) * E_DIM) + t32;
    __half2* dp = (__half2*)(g_kvc + ((size_t)b * IDXCAP + row) * E_DIM) + t32 * 2;
#pragma unroll
    for (int j = 0; j < 8; j++) {
        float4 v = sp[j * 32];
        dp[j * 64]     = __float22half2_rn(make_float2(v.x, v.y));
        dp[j * 64 + 1] = __float22half2_rn(make_float2(v.z, v.w));
    }
}

// ---------------- mask compaction ----------------
__global__ void __launch_bounds__(1024) compact_kernel(const int* __restrict__ mask) {
    const int b   = blockIdx.x;
    const int tid = threadIdx.x;
    const int lane = tid & 31, warp = tid >> 5;
    const int* m = mask + (size_t)b * SEQ_KV;
    __shared__ int warpSums[32];

    int v[4];
    int base = tid * 4;
    int cnt = 0;
#pragma unroll
    for (int i = 0; i < 4; i++) { v[i] = (m[base + i] != 0); cnt += v[i]; }

    int x = cnt;
#pragma unroll
    for (int off = 1; off < 32; off <<= 1) {
        int y = __shfl_up_sync(0xffffffffu, x, off);
        if (lane >= off) x += y;
    }
    if (lane == 31) warpSums[warp] = x;
    __syncthreads();
    if (warp == 0) {
        int wsum = warpSums[lane];
#pragma unroll
        for (int off = 1; off < 32; off <<= 1) {
            int y = __shfl_up_sync(0xffffffffu, wsum, off);
            if (lane >= off) wsum += y;
        }
        warpSums[lane] = wsum;
    }
    __syncthreads();
    int warpBase = (warp == 0) ? 0 : warpSums[warp - 1];
    int pos = warpBase + x - cnt;
#pragma unroll
    for (int i = 0; i < 4; i++) {
        if (v[i]) {
            g_idx[b][pos]  = base + i;
            g_bias[b][pos] = -SM_SHIFT * LOG2E;
            pos++;
        }
    }
    __syncthreads();
    int total  = warpSums[31];
    int padded = (total + 63) & ~63;
    for (int j = total + tid; j < padded; j += 1024) {
        g_idx[b][j]  = 0;
        g_bias[b][j] = -100.0f;
    }
    if (tid == 0) g_ntiles[b] = padded >> 6;
}

// ---------------- fp16 GEMM ----------------
#define HA_STG (64 * 72)
#define HB_STG (128 * 72)
#define GEMM_SMEM_BYTES (3 * (HA_STG + HB_STG) * 2)

template <int MODE>
__global__ void __launch_bounds__(256, 2) gemm_h_kernel(
    const __half* __restrict__ A, const __half* __restrict__ W,
    const float* __restrict__ bias, void* __restrict__ Cv,
    int S, float outScale)
{
    extern __shared__ char smraw[];
    __half* As = (__half*)smraw;
    __half* Bs = As + 3 * HA_STG;

    const int tid  = threadIdx.x;
    const int lane = tid & 31;
    const int warp = tid >> 5;
    const int lq   = lane >> 2;
    const int kq   = lane & 3;
    const int bm   = blockIdx.x * 64;
    const int bn   = blockIdx.y * 128;
    const int wm   = (warp & 1) * 32;
    const int wn   = (warp >> 1) * 32;

    auto issue = [&](int kt, int s) {
#pragma unroll
        for (int p = 0; p < 2; p++) {
            int i   = p * 256 + tid;
            int row = i >> 3;
            int c8  = i & 7;
            cpasync16h(As + s * HA_STG + row * 72 + c8 * 8,
                       A + (size_t)(bm + row) * E_DIM + kt * 64 + c8 * 8);
        }
#pragma unroll
        for (int p = 0; p < 4; p++) {
            int i   = p * 256 + tid;
            int row = i >> 3;
            int c8  = i & 7;
            cpasync16h(Bs + s * HB_STG + row * 72 + c8 * 8,
                       W + (size_t)(bn + row) * E_DIM + kt * 64 + c8 * 8);
        }
        CP_COMMIT();
    };

    float acc[2][4][4];
#pragma unroll
    for (int mt = 0; mt < 2; mt++)
#pragma unroll
        for (int nt = 0; nt < 4; nt++)
#pragma unroll
            for (int r = 0; r < 4; r++) acc[mt][nt][r] = 0.0f;

    const int aOff = (wm + (lane & 15)) * 72 + ((lane >> 4) << 3);
    const int bOff = (wn + (lane & 7) + ((lane & 16) >> 1)) * 72 + (lane & 8);

    issue(0, 0);
    issue(1, 1);

#pragma unroll 1
    for (int kt = 0; kt < 16; kt++) {
        if (kt < 15) { CP_WAIT(1); } else { CP_WAIT(0); }
        __syncthreads();
        if (kt + 2 < 16) issue(kt + 2, (kt + 2) % 3);

        const int st = kt % 3;
        uint32_t aB = (uint32_t)__cvta_generic_to_shared(As + st * HA_STG);
        uint32_t bB = (uint32_t)__cvta_generic_to_shared(Bs + st * HB_STG);

#pragma unroll
        for (int ks = 0; ks < 4; ks++) {
            const int k0 = ks * 16;
            unsigned af[2][4];
            ldsm4(af[0], aB + 2u * (aOff + k0));
            ldsm4(af[1], aB + 2u * (aOff + 16 * 72 + k0));
#pragma unroll
            for (int np = 0; np < 2; np++) {
                unsigned bf[4];
                ldsm4(bf, bB + 2u * (bOff + np * 16 * 72 + k0));
                mma16(acc[0][2 * np],     af[0], bf[0], bf[1]);
                mma16(acc[1][2 * np],     af[1], bf[0], bf[1]);
                mma16(acc[0][2 * np + 1], af[0], bf[2], bf[3]);
                mma16(acc[1][2 * np + 1], af[1], bf[2], bf[3]);
            }
        }
    }

#pragma unroll
    for (int mt = 0; mt < 2; mt++) {
        int rA = bm + wm + mt * 16 + lq;
#pragma unroll
        for (int nt = 0; nt < 4; nt++) {
            int c0 = bn + wn + nt * 8 + 2 * kq;
            float b0 = bias[c0], b1 = bias[c0 + 1];
            float v0 = (acc[mt][nt][0] + b0) * outScale;
            float v1 = (acc[mt][nt][1] + b1) * outScale;
            float v2 = (acc[mt][nt][2] + b0) * outScale;
            float v3 = (acc[mt][nt][3] + b1) * outScale;
            if (MODE == 1) {
                __half* C = (__half*)Cv;
                int bb = rA / S, ss = rA - bb * S;
                int h = c0 >> 6, d = c0 & 63;
                __half2* p0 = (__half2*)(C + (((size_t)bb * NHEAD + h) * S + ss) * HDIM + d);
                *p0 = __float22half2_rn(make_float2(v0, v1));
                int rA2 = rA + 8;
                int bb2 = rA2 / S, ss2 = rA2 - bb2 * S;
                __half2* p1 = (__half2*)(C + (((size_t)bb2 * NHEAD + h) * S + ss2) * HDIM + d);
                *p1 = __float22half2_rn(make_float2(v2, v3));
            } else {
                float* C = (float*)Cv;
                *(float2*)(C + (size_t)rA * E_DIM + c0)       = make_float2(v0, v1);
                *(float2*)(C + (size_t)(rA + 8) * E_DIM + c0) = make_float2(v2, v3);
            }
        }
    }
}

// ---------------- merged K+V GEMM ----------------
__global__ void __launch_bounds__(256, 2) gemm_kv_kernel(
    const __half* __restrict__ A,
    const __half* __restrict__ Wk, const __half* __restrict__ Wv,
    const float* __restrict__ bk, const float* __restrict__ bv,
    __half* __restrict__ Kp, __half* __restrict__ Vp)
{
    const int tile = blockIdx.x;
    const int b    = tile >> 6;
    const int lt   = tile & 63;
    if (lt >= g_ntiles[b]) return;

    const bool isV = blockIdx.y >= 8;
    const __half* W   = isV ? Wv : Wk;
    const float* bias = isV ? bv : bk;
    const int bn      = (blockIdx.y & 7) * 128;

    extern __shared__ char smraw[];
    __half* As = (__half*)smraw;
    __half* Bs = As + 3 * HA_STG;

    const int tid  = threadIdx.x;
    const int lane = tid & 31;
    const int warp = tid >> 5;
    const int lq   = lane >> 2;
    const int kq   = lane & 3;
    const int wm   = (warp & 1) * 32;
    const int wn   = (warp >> 1) * 32;

    const __half* Ab = A + ((size_t)b * IDXCAP + lt * 64) * E_DIM;

    auto issue = [&](int kt, int s) {
#pragma unroll
        for (int p = 0; p < 2; p++) {
            int i   = p * 256 + tid;
            int row = i >> 3;
            int c8  = i & 7;
            cpasync16h(As + s * HA_STG + row * 72 + c8 * 8,
                       Ab + (size_t)row * E_DIM + kt * 64 + c8 * 8);
        }
#pragma unroll
        for (int p = 0; p < 4; p++) {
            int i   = p * 256 + tid;
            int row = i >> 3;
            int c8  = i & 7;
            cpasync16h(Bs + s * HB_STG + row * 72 + c8 * 8,
                       W + (size_t)(bn + row) * E_DIM + kt * 64 + c8 * 8);
        }
        CP_COMMIT();
    };

    float acc[2][4][4];
#pragma unroll
    for (int mt = 0; mt < 2; mt++)
#pragma unroll
        for (int nt = 0; nt < 4; nt++)
#pragma unroll
            for (int r = 0; r < 4; r++) acc[mt][nt][r] = 0.0f;

    const int aOff = (wm + (lane & 15)) * 72 + ((lane >> 4) << 3);
    const int bOff = (wn + (lane & 7) + ((lane & 16) >> 1)) * 72 + (lane & 8);

    issue(0, 0);
    issue(1, 1);

#pragma unroll 1
    for (int kt = 0; kt < 16; kt++) {
        if (kt < 15) { CP_WAIT(1); } else { CP_WAIT(0); }
        __syncthreads();
        if (kt + 2 < 16) issue(kt + 2, (kt + 2) % 3);

        const int st = kt % 3;
        uint32_t aB = (uint32_t)__cvta_generic_to_shared(As + st * HA_STG);
        uint32_t bB = (uint32_t)__cvta_generic_to_shared(Bs + st * HB_STG);

#pragma unroll
        for (int ks = 0; ks < 4; ks++) {
            const int k0 = ks * 16;
            unsigned af[2][4];
            ldsm4(af[0], aB + 2u * (aOff + k0));
            ldsm4(af[1], aB + 2u * (aOff + 16 * 72 + k0));
#pragma unroll
            for (int np = 0; np < 2; np++) {
                unsigned bf[4];
                ldsm4(bf, bB + 2u * (bOff + np * 16 * 72 + k0));
                mma16(acc[0][2 * np],     af[0], bf[0], bf[1]);
                mma16(acc[1][2 * np],     af[1], bf[0], bf[1]);
                mma16(acc[0][2 * np + 1], af[0], bf[2], bf[3]);
                mma16(acc[1][2 * np + 1], af[1], bf[2], bf[3]);
            }
        }
    }

#pragma unroll
    for (int mt = 0; mt < 2; mt++) {
        int sRow = lt * 64 + wm + mt * 16 + lq;
#pragma unroll
        for (int nt = 0; nt < 4; nt++) {
            int c0 = bn + wn + nt * 8 + 2 * kq;
            int h = c0 >> 6, d = c0 & 63;
            float b0 = bias[c0], b1 = bias[c0 + 1];
            __half h0 = __float2half_rn(acc[mt][nt][0] + b0);
            __half h1 = __float2half_rn(acc[mt][nt][1] + b1);
            __half h2 = __float2half_rn(acc[mt][nt][2] + b0);
            __half h3 = __float2half_rn(acc[mt][nt][3] + b1);
            if (isV) {
                __half* base = Vp + ((size_t)b * NHEAD + h) * (size_t)HDIM * SEQ_KV;
                base[(size_t)d * SEQ_KV + sRow]           = h0;
                base[(size_t)(d + 1) * SEQ_KV + sRow]     = h1;
                base[(size_t)d * SEQ_KV + sRow + 8]       = h2;
                base[(size_t)(d + 1) * SEQ_KV + sRow + 8] = h3;
            } else {
                __half2* p0 = (__half2*)(Kp + (((size_t)b * NHEAD + h) * SEQ_KV + sRow) * HDIM + d);
                *p0 = __halves2half2(h0, h1);
                __half2* p1 = (__half2*)(Kp + (((size_t)b * NHEAD + h) * SEQ_KV + sRow + 8) * HDIM + d);
                *p1 = __halves2half2(h2, h3);
            }
        }
    }
}

// ---------------- fp16 flash attention (non-split, exp2.f16x2, l-via-mma) ----------------
// V tile 80 rows: 0..63 = V data (d-major), 64 = ones (l column), 65..79 = 0.
#define HSTR 72
#define V2ROWS 80
#define QOFF_H 0
#define KOFF_H (128 * HSTR)
#define VOFF_H (KOFF_H + 2 * 64 * HSTR)
#define TOT_H  (VOFF_H + 2 * V2ROWS * HSTR)
#define MOFF_B (TOT_H * 2)
#define ATT_SMEM_BYTES (MOFF_B + 2 * 64 * 4)

__global__ void __launch_bounds__(128, 3) attn_kernel()
{
    extern __shared__ char smraw[];
    __half* smh  = (__half*)smraw;
    float*  mskF = (float*)(smraw + MOFF_B);

    const int tid  = threadIdx.x;
    const int lane = tid & 31;
    const int warp = tid >> 5;
    const int lq   = lane >> 2;
    const int kq   = lane & 3;
    const int qt = blockIdx.x;
    const int h = blockIdx.y, b = blockIdx.z;

    const int nt = g_ntiles[b];

    const __half* Qg = g_Qp + (((size_t)b * NHEAD + h) * SEQ_Q + qt * 128) * HDIM;
    const __half* Kg = g_Kp + ((size_t)b * NHEAD + h) * SEQ_KV * HDIM;
    const __half* Vg = g_Vp + ((size_t)b * NHEAD + h) * (size_t)HDIM * SEQ_KV;

#pragma unroll
    for (int p = 0; p < 8; p++) {
        int i   = p * 128 + tid;
        int row = i >> 3;
        int c8  = i & 7;
        cpasync16h(smh + QOFF_H + row * HSTR + c8 * 8, Qg + row * HDIM + c8 * 8);
    }
    CP_COMMIT();
    CP_WAIT(0);
    __syncthreads();

    const int r0 = warp * 32;
    unsigned qf[2][4][4];
    {
        uint32_t qB = (uint32_t)__cvta_generic_to_shared(smh + QOFF_H);
        const int qOff = (r0 + (lane & 15)) * HSTR + ((lane >> 4) << 3);
#pragma unroll
        for (int rb = 0; rb < 2; rb++)
#pragma unroll
            for (int ks = 0; ks < 4; ks++)
                ldsm4(qf[rb][ks], qB + 2u * (qOff + rb * 16 * HSTR + ks * 16));
    }
    __syncthreads();

    // init V pad rows (64 = ones, 65..79 = 0) in both stage buffers
    {
        const __half one  = __float2half_rn(1.0f);
        const __half zero = __float2half_rn(0.0f);
        for (int i = tid; i < 2 * 16 * HSTR; i += 128) {
            int s  = i / (16 * HSTR);
            int rr = (i % (16 * HSTR)) / HSTR;
            int cc = i % HSTR;
            smh[VOFF_H + s * V2ROWS * HSTR + (64 + rr) * HSTR + cc] = (rr == 0) ? one : zero;
        }
    }

    auto issue = [&](int kt, int s) {
        const __half* kp = Kg + (size_t)kt * 64 * HDIM;
        const __half* vp = Vg + (size_t)kt * 64;
#pragma unroll
        for (int p = 0; p < 4; p++) {
            int i   = p * 128 + tid;
            int row = i >> 3;
            int c8  = i & 7;
            cpasync16h(smh + KOFF_H + s * 64 * HSTR + row * HSTR + c8 * 8,
                       kp + (size_t)row * HDIM + c8 * 8);
            cpasync16h(smh + VOFF_H + s * V2ROWS * HSTR + row * HSTR + c8 * 8,
                       vp + (size_t)row * SEQ_KV + c8 * 8);
        }
        if (tid < 64) mskF[s * 64 + tid] = g_bias[b][kt * 64 + tid];
        CP_COMMIT();
    };

    float o[2][9][4];
#pragma unroll
    for (int rb = 0; rb < 2; rb++)
#pragma unroll
        for (int ntl = 0; ntl < 9; ntl++)
#pragma unroll
            for (int r = 0; r < 4; r++) o[rb][ntl][r] = 0.0f;

    issue(0, 0);
    if (nt > 1) issue(1, 1);

    const int kvOff = ((lane & 7) + ((lane & 16) >> 1)) * HSTR + (lane & 8);
    const int pOff  = (r0 + (lane & 15)) * HSTR + ((lane >> 4) << 3);

#pragma unroll 1
    for (int it = 0; it < nt; it++) {
        if (it + 1 < nt) { CP_WAIT(1); } else { CP_WAIT(0); }
        __syncthreads();
        const int s = it & 1;
        const float* msk = mskF + s * 64;
        uint32_t kB = (uint32_t)__cvta_generic_to_shared(smh + KOFF_H + s * 64 * HSTR);
        uint32_t vB = (uint32_t)__cvta_generic_to_shared(smh + VOFF_H + s * V2ROWS * HSTR);
        uint32_t pB = (uint32_t)__cvta_generic_to_shared(smh + QOFF_H);

        float sacc[2][8][4];
#pragma unroll
        for (int rb = 0; rb < 2; rb++)
#pragma unroll
            for (int ntl = 0; ntl < 8; ntl++)
#pragma unroll
                for (int r = 0; r < 4; r++) sacc[rb][ntl][r] = 0.0f;

#pragma unroll
        for (int ks = 0; ks < 4; ks++) {
            const int k0 = ks * 16;
#pragma unroll
            for (int np = 0; np < 4; np++) {
                unsigned kf[4];
                ldsm4(kf, kB + 2u * (kvOff + np * 16 * HSTR + k0));
                mma16(sacc[0][2 * np],     qf[0][ks], kf[0], kf[1]);
                mma16(sacc[1][2 * np],     qf[1][ks], kf[0], kf[1]);
                mma16(sacc[0][2 * np + 1], qf[0][ks], kf[2], kf[3]);
                mma16(sacc[1][2 * np + 1], qf[1][ks], kf[2], kf[3]);
            }
        }

#pragma unroll
        for (int ntl = 0; ntl < 8; ntl++) {
            float m0 = msk[ntl * 8 + 2 * kq];
            float m1 = msk[ntl * 8 + 2 * kq + 1];
#pragma unroll
            for (int rb = 0; rb < 2; rb++) {
                float u0 = fmaf(sacc[rb][ntl][0], LOG2E, m0);
                float u1 = fmaf(sacc[rb][ntl][1], LOG2E, m1);
                float u2 = fmaf(sacc[rb][ntl][2], LOG2E, m0);
                float u3 = fmaf(sacc[rb][ntl][3], LOG2E, m1);
                int rr = r0 + rb * 16;
                *(unsigned*)(smh + QOFF_H + (rr + lq) * HSTR + ntl * 8 + 2 * kq)     = exp2h2(u0, u1);
                *(unsigned*)(smh + QOFF_H + (rr + 8 + lq) * HSTR + ntl * 8 + 2 * kq) = exp2h2(u2, u3);
            }
        }
        __syncwarp();

#pragma unroll
        for (int ks = 0; ks < 4; ks++) {
            const int k0 = ks * 16;
            unsigned pf[2][4];
            ldsm4(pf[0], pB + 2u * (pOff + k0));
            ldsm4(pf[1], pB + 2u * (pOff + 16 * HSTR + k0));
#pragma unroll
            for (int np = 0; np < 4; np++) {
                unsigned vf[4];
                ldsm4(vf, vB + 2u * (kvOff + np * 16 * HSTR + k0));
                mma16(o[0][2 * np],     pf[0], vf[0], vf[1]);
                mma16(o[1][2 * np],     pf[1], vf[0], vf[1]);
                mma16(o[0][2 * np + 1], pf[0], vf[2], vf[3]);
                mma16(o[1][2 * np + 1], pf[1], vf[2], vf[3]);
            }
            {
                unsigned vf[4];
                ldsm4(vf, vB + 2u * (kvOff + 4 * 16 * HSTR + k0));
                mma16(o[0][8], pf[0], vf[0], vf[1]);
                mma16(o[1][8], pf[1], vf[0], vf[1]);
            }
        }
        __syncthreads();
        if (it + 2 < nt) issue(it + 2, s);
    }

    // normalize (l from mma column, broadcast from kq==0 lane) and write fp16 [B,SQ,E]
    __half* outBase = g_attnh + (size_t)b * SEQ_Q * E_DIM;
#pragma unroll
    for (int rb = 0; rb < 2; rb++) {
        float lA = __shfl_sync(0xffffffffu, o[rb][8][0], lane & ~3);
        float lB = __shfl_sync(0xffffffffu, o[rb][8][2], lane & ~3);
        float rA = 1.0f / lA, rB = 1.0f / lB;
        int qA = qt * 128 + r0 + rb * 16 + lq;
#pragma unroll
        for (int ntl = 0; ntl < 8; ntl++) {
            int c = h * HDIM + ntl * 8 + 2 * kq;
            *(__half2*)(outBase + (size_t)qA * E_DIM + c) =
                __float22half2_rn(make_float2(o[rb][ntl][0] * rA, o[rb][ntl][1] * rA));
            *(__half2*)(outBase + (size_t)(qA + 8) * E_DIM + c) =
                __float22half2_rn(make_float2(o[rb][ntl][2] * rB, o[rb][ntl][3] * rB));
        }
    }
}

// ---------------- residual + LayerNorm ----------------
__global__ void __launch_bounds__(256) ln_kernel(
    const float* __restrict__ query, const float* __restrict__ proj,
    const float* __restrict__ gamma, const float* __restrict__ beta,
    float* __restrict__ out)
{
    __shared__ float rs[8], rs2[8];
    const int row = blockIdx.x, tid = threadIdx.x;
    const int lane = tid & 31, warp = tid >> 5;
    const size_t base = (size_t)row * E_DIM + tid * 4;

    float4 q = *(const float4*)(query + base);
    float4 p = *(const float4*)(proj + base);
    float x0 = q.x + p.x, x1 = q.y + p.y, x2 = q.z + p.z, x3 = q.w + p.w;
    float s  = x0 + x1 + x2 + x3;
    float s2 = x0 * x0 + x1 * x1 + x2 * x2 + x3 * x3;
#pragma unroll
    for (int off = 16; off; off >>= 1) {
        s  += __shfl_xor_sync(0xffffffffu, s, off);
        s2 += __shfl_xor_sync(0xffffffffu, s2, off);
    }
    if (lane == 0) { rs[warp] = s; rs2[warp] = s2; }
    __syncthreads();
    s = 0.0f; s2 = 0.0f;
#pragma unroll
    for (int i = 0; i < 8; i++) { s += rs[i]; s2 += rs2[i]; }

    float mean = s * (1.0f / E_DIM);
    float var  = s2 * (1.0f / E_DIM) - mean * mean;
    float rstd = rsqrtf(var + LN_EPS);

    float4 g  = *(const float4*)(gamma + tid * 4);
    float4 bb = *(const float4*)(beta + tid * 4);
    float4 r;
    r.x = (x0 - mean) * rstd * g.x + bb.x;
    r.y = (x1 - mean) * rstd * g.y + bb.y;
    r.z = (x2 - mean) * rstd * g.z + bb.z;
    r.w = (x3 - mean) * rstd * g.w + bb.w;
    *(float4*)(out + base) = r;
}

// ---------------- launch (fork-join dual stream, graph-capturable) ----------------
extern "C" void kernel_launch(void* const* d_in, const int* in_sizes, int n_in,
                              void* d_out, int out_size)
{
    const float* query     = (const float*)d_in[0];
    const float* key_value = (const float*)d_in[1];
    const int*   kvmask    = (const int*)d_in[2];
    const float* Wq = (const float*)d_in[3];
    const float* bq = (const float*)d_in[4];
    const float* Wk = (const float*)d_in[5];
    const float* bk = (const float*)d_in[6];
    const float* Wv = (const float*)d_in[7];
    const float* bv = (const float*)d_in[8];
    const float* Wo = (const float*)d_in[9];
    const float* bo = (const float*)d_in[10];
    const float* gamma = (const float*)d_in[11];
    const float* beta  = (const float*)d_in[12];
    float* out = (float*)d_out;

    __half *qh, *wh, *Qp, *Kp, *Vp, *attnh, *kvc;
    float *proj;
    cudaGetSymbolAddress((void**)&qh, g_qh);
    cudaGetSymbolAddress((void**)&wh, g_wh);
    cudaGetSymbolAddress((void**)&Qp, g_Qp);
    cudaGetSymbolAddress((void**)&Kp, g_Kp);
    cudaGetSymbolAddress((void**)&Vp, g_Vp);
    cudaGetSymbolAddress((void**)&attnh, g_attnh);
    cudaGetSymbolAddress((void**)&proj, g_proj);
    cudaGetSymbolAddress((void**)&kvc, g_kvc);

    cudaFuncSetAttribute(gemm_h_kernel<0>,
                         cudaFuncAttributeMaxDynamicSharedMemorySize, GEMM_SMEM_BYTES);
    cudaFuncSetAttribute(gemm_h_kernel<1>,
                         cudaFuncAttributeMaxDynamicSharedMemorySize, GEMM_SMEM_BYTES);
    cudaFuncSetAttribute(gemm_kv_kernel,
                         cudaFuncAttributeMaxDynamicSharedMemorySize, GEMM_SMEM_BYTES);
    cudaFuncSetAttribute(attn_kernel,
                         cudaFuncAttributeMaxDynamicSharedMemorySize, ATT_SMEM_BYTES);

    // lazily-created side stream + events (resources only; per-call work is identical)
    static cudaStream_t s1 = nullptr;
    static cudaEvent_t e0 = nullptr, ew = nullptr, eq = nullptr;
    if (s1 == nullptr) {
        cudaStreamCreateWithFlags(&s1, cudaStreamNonBlocking);
        cudaEventCreateWithFlags(&e0, cudaEventDisableTiming);
        cudaEventCreateWithFlags(&ew, cudaEventDisableTiming);
        cudaEventCreateWithFlags(&eq, cudaEventDisableTiming);
    }

    // fork
    cudaEventRecord(e0, 0);
    cudaStreamWaitEvent(s1, e0, 0);

    // side chain: weight+query conversion, Q projection
    conv_w<<<dim3(E_DIM * E_DIM / 4 / 1024, 4), 256, 0, s1>>>(Wq, Wk, Wv, Wo, wh);
    cudaEventRecord(ew, s1);
    conv_one<<<BATCH * SEQ_Q * E_DIM / 4 / 1024, 256, 0, s1>>>(query, qh);
    gemm_h_kernel<1><<<dim3(BATCH * SEQ_Q / 64, 8), 256, GEMM_SMEM_BYTES, s1>>>(
        qh, wh, bq, Qp, SEQ_Q, 0.125f);
    cudaEventRecord(eq, s1);

    // main chain: compaction, kv gather-convert, KV projections
    compact_kernel<<<BATCH, 1024>>>(kvmask);
    conv_kvc<<<dim3(SEQ_KV / 8, BATCH), 256>>>(key_value);
    cudaStreamWaitEvent(0, ew, 0);   // Wk/Wv ready
    gemm_kv_kernel<<<dim3(BATCH * 64, 16), 256, GEMM_SMEM_BYTES>>>(
        kvc, wh + (size_t)E_DIM * E_DIM, wh + 2 * (size_t)E_DIM * E_DIM, bk, bv, Kp, Vp);

    // join: attention needs Qp too
    cudaStreamWaitEvent(0, eq, 0);
    attn_kernel<<<dim3(SEQ_Q / 128, NHEAD, BATCH), 128, ATT_SMEM_BYTES>>>();

    // output projection + LN (Wo ready via ew wait above)
    gemm_h_kernel<0><<<dim3(BATCH * SEQ_Q / 64, 8), 256, GEMM_SMEM_BYTES>>>(
        attnh, wh + 3 * (size_t)E_DIM * E_DIM, bo, proj, SEQ_Q, 1.0f);
    ln_kernel<<<BATCH * SEQ_Q, 256>>>(query, proj, gamma, beta, out);
}